// round 10
// baseline (speedup 1.0000x reference)
#include <cuda_runtime.h>
#include <cstdint>

#define T_LEN 1024
#define BATCH 2
#define EMB 1024
#define HEADS 16
#define HDIM 64
#define MROWS (T_LEN * BATCH)   // 2048
#define BH (BATCH * HEADS)      // 32

// ---------------- scratch (device globals; no allocation) ----------------
__device__ float sc_qkv[MROWS * 3 * EMB];   // g-stream: q | gk | gv   (2048 x 3072)
__device__ float sc_kvh[MROWS * 2 * EMB];   // h-stream: hk | hv       (2048 x 2048)
__device__ float sc_Sg[33554432];           // g scores / probs  [BH,T,T]
__device__ float sc_Sh[33554432];           // h scores / sample [BH,T,T]
__device__ float sc_ag[MROWS * EMB];        // merged g attention out [T*B, E]
__device__ float sc_ah[MROWS * EMB];        // merged h attention out

// ---------------- threefry2x32 (JAX, key = (0, 42)) -----------------------
// Full 20-round threefry2x32 returning BOTH output words.
// ks0 = 0, ks1 = 42, ks2 = 0x1BD11BDA ^ 0 ^ 42 = 0x1BD11BF0
static __device__ __forceinline__ uint2 threefry2x32_both(uint32_t c0, uint32_t c1) {
    const uint32_t ks1 = 42u;
    const uint32_t ks2 = 0x1BD11BF0u;
    uint32_t x0 = c0;            // + ks0 (=0)
    uint32_t x1 = c1 + ks1;
#define TF_R(r) { x0 += x1; x1 = __funnelshift_l(x1, x1, (r)); x1 ^= x0; }
    TF_R(13) TF_R(15) TF_R(26) TF_R(6)   x0 += ks1; x1 += ks2 + 1u;
    TF_R(17) TF_R(29) TF_R(16) TF_R(24)  x0 += ks2; x1 += 0u  + 2u;
    TF_R(13) TF_R(15) TF_R(26) TF_R(6)   x0 += 0u;  x1 += ks1 + 3u;
    TF_R(17) TF_R(29) TF_R(16) TF_R(24)  x0 += ks1; x1 += ks2 + 4u;
    TF_R(13) TF_R(15) TF_R(26) TF_R(6)   x0 += ks2; x1 += 0u  + 5u;
#undef TF_R
    return make_uint2(x0, x1);
}

// JAX partitionable mode (jax_threefry_partitionable=True, modern default):
// counts = hi/lo 32-bit words of 64-bit iota -> (0, i) for i < 2^32;
// 32-bit output = bits1 ^ bits2 (XOR of BOTH threefry output words).
static __device__ __forceinline__ uint32_t jax_bits_partitionable_xor(uint32_t idx) {
    uint2 w = threefry2x32_both(0u, idx);
    return w.x ^ w.y;
}

// ---------------- register-tiled SGEMM: C[M,N] = A[M,K] @ W[N,K]^T + bias ---
// epilogue: columns n < scale_cols multiplied by 0.125 (q * d^-0.5)
__global__ __launch_bounds__(256, 2) void sgemm_bias(
    const float* __restrict__ A, const float* __restrict__ W,
    const float* __restrict__ bias, float* __restrict__ C,
    int N, int K, int scale_cols)
{
    __shared__ float As[16][132];
    __shared__ float Bs[16][132];
    const int bm = blockIdx.y * 128;
    const int bn = blockIdx.x * 128;
    const int tid = threadIdx.x;
    const int tx = tid & 15, ty = tid >> 4;

    float acc[8][8];
#pragma unroll
    for (int i = 0; i < 8; i++)
#pragma unroll
        for (int j = 0; j < 8; j++) acc[i][j] = 0.f;

    const float* Ab = A + (size_t)bm * K;
    const float* Wb = W + (size_t)bn * K;

    for (int k0 = 0; k0 < K; k0 += 16) {
#pragma unroll
        for (int r = 0; r < 2; r++) {
            int idx = tid + r * 256;       // 0..511
            int row = idx >> 2;            // 0..127
            int kq  = (idx & 3) << 2;      // 0,4,8,12
            float4 va = *(const float4*)(Ab + (size_t)row * K + k0 + kq);
            As[kq+0][row] = va.x; As[kq+1][row] = va.y;
            As[kq+2][row] = va.z; As[kq+3][row] = va.w;
            float4 vb = *(const float4*)(Wb + (size_t)row * K + k0 + kq);
            Bs[kq+0][row] = vb.x; Bs[kq+1][row] = vb.y;
            Bs[kq+2][row] = vb.z; Bs[kq+3][row] = vb.w;
        }
        __syncthreads();
#pragma unroll
        for (int k = 0; k < 16; k++) {
            float ra[8], rb[8];
            *(float4*)(ra)     = *(const float4*)&As[k][ty * 8];
            *(float4*)(ra + 4) = *(const float4*)&As[k][ty * 8 + 4];
            *(float4*)(rb)     = *(const float4*)&Bs[k][tx * 8];
            *(float4*)(rb + 4) = *(const float4*)&Bs[k][tx * 8 + 4];
#pragma unroll
            for (int i = 0; i < 8; i++)
#pragma unroll
                for (int j = 0; j < 8; j++)
                    acc[i][j] = fmaf(ra[i], rb[j], acc[i][j]);
        }
        __syncthreads();
    }
#pragma unroll
    for (int i = 0; i < 8; i++) {
        int m = bm + ty * 8 + i;
#pragma unroll
        for (int j = 0; j < 8; j += 4) {
            int n = bn + tx * 8 + j;
            float4 o;
            o.x = acc[i][j+0] + bias[n+0];
            o.y = acc[i][j+1] + bias[n+1];
            o.z = acc[i][j+2] + bias[n+2];
            o.w = acc[i][j+3] + bias[n+3];
            if (n < scale_cols) { o.x *= 0.125f; o.y *= 0.125f; o.z *= 0.125f; o.w *= 0.125f; }
            *(float4*)(C + (size_t)m * N + n) = o;
        }
    }
}

// ---------------- dual-stream scores: Sg/Sh[bh,t,s] = sum_j q*k -----------
__global__ __launch_bounds__(256) void scores_kernel()
{
    __shared__ float Qs[64][65];   // [j][t]
    __shared__ float Ks[64][65];   // [j][s] (reused for gk then hk)
    const int s0 = blockIdx.x * 64;
    const int t0 = blockIdx.y * 64;
    const int bh = blockIdx.z;
    const int b = bh >> 4, hh = bh & 15;
    const int tid = threadIdx.x;
    const int tx = tid & 15, ty = tid >> 4;
    const int col = hh * HDIM;

#pragma unroll
    for (int r = 0; r < 4; r++) {
        int fi = tid + r * 256;
        int row = fi >> 4;
        int jq = (fi & 15) << 2;
        float4 q = *(const float4*)(sc_qkv + (size_t)((t0 + row) * BATCH + b) * 3072 + col + jq);
        Qs[jq+0][row] = q.x; Qs[jq+1][row] = q.y; Qs[jq+2][row] = q.z; Qs[jq+3][row] = q.w;
        float4 kg = *(const float4*)(sc_qkv + (size_t)((s0 + row) * BATCH + b) * 3072 + EMB + col + jq);
        Ks[jq+0][row] = kg.x; Ks[jq+1][row] = kg.y; Ks[jq+2][row] = kg.z; Ks[jq+3][row] = kg.w;
    }
    __syncthreads();

    float accg[4][4] = {};
#pragma unroll 8
    for (int j = 0; j < 64; j++) {
        float q0 = Qs[j][ty*4+0], q1 = Qs[j][ty*4+1], q2 = Qs[j][ty*4+2], q3 = Qs[j][ty*4+3];
        float k0 = Ks[j][tx*4+0], k1 = Ks[j][tx*4+1], k2 = Ks[j][tx*4+2], k3 = Ks[j][tx*4+3];
        accg[0][0] = fmaf(q0,k0,accg[0][0]); accg[0][1] = fmaf(q0,k1,accg[0][1]);
        accg[0][2] = fmaf(q0,k2,accg[0][2]); accg[0][3] = fmaf(q0,k3,accg[0][3]);
        accg[1][0] = fmaf(q1,k0,accg[1][0]); accg[1][1] = fmaf(q1,k1,accg[1][1]);
        accg[1][2] = fmaf(q1,k2,accg[1][2]); accg[1][3] = fmaf(q1,k3,accg[1][3]);
        accg[2][0] = fmaf(q2,k0,accg[2][0]); accg[2][1] = fmaf(q2,k1,accg[2][1]);
        accg[2][2] = fmaf(q2,k2,accg[2][2]); accg[2][3] = fmaf(q2,k3,accg[2][3]);
        accg[3][0] = fmaf(q3,k0,accg[3][0]); accg[3][1] = fmaf(q3,k1,accg[3][1]);
        accg[3][2] = fmaf(q3,k2,accg[3][2]); accg[3][3] = fmaf(q3,k3,accg[3][3]);
    }
    __syncthreads();

#pragma unroll
    for (int r = 0; r < 4; r++) {
        int fi = tid + r * 256;
        int row = fi >> 4;
        int jq = (fi & 15) << 2;
        float4 kh = *(const float4*)(sc_kvh + (size_t)((s0 + row) * BATCH + b) * 2048 + col + jq);
        Ks[jq+0][row] = kh.x; Ks[jq+1][row] = kh.y; Ks[jq+2][row] = kh.z; Ks[jq+3][row] = kh.w;
    }
    __syncthreads();

    float acch[4][4] = {};
#pragma unroll 8
    for (int j = 0; j < 64; j++) {
        float q0 = Qs[j][ty*4+0], q1 = Qs[j][ty*4+1], q2 = Qs[j][ty*4+2], q3 = Qs[j][ty*4+3];
        float k0 = Ks[j][tx*4+0], k1 = Ks[j][tx*4+1], k2 = Ks[j][tx*4+2], k3 = Ks[j][tx*4+3];
        acch[0][0] = fmaf(q0,k0,acch[0][0]); acch[0][1] = fmaf(q0,k1,acch[0][1]);
        acch[0][2] = fmaf(q0,k2,acch[0][2]); acch[0][3] = fmaf(q0,k3,acch[0][3]);
        acch[1][0] = fmaf(q1,k0,acch[1][0]); acch[1][1] = fmaf(q1,k1,acch[1][1]);
        acch[1][2] = fmaf(q1,k2,acch[1][2]); acch[1][3] = fmaf(q1,k3,acch[1][3]);
        acch[2][0] = fmaf(q2,k0,acch[2][0]); acch[2][1] = fmaf(q2,k1,acch[2][1]);
        acch[2][2] = fmaf(q2,k2,acch[2][2]); acch[2][3] = fmaf(q2,k3,acch[2][3]);
        acch[3][0] = fmaf(q3,k0,acch[3][0]); acch[3][1] = fmaf(q3,k1,acch[3][1]);
        acch[3][2] = fmaf(q3,k2,acch[3][2]); acch[3][3] = fmaf(q3,k3,acch[3][3]);
    }

    size_t obase = (size_t)bh * T_LEN * T_LEN;
#pragma unroll
    for (int i = 0; i < 4; i++) {
        size_t off = obase + (size_t)(t0 + ty * 4 + i) * T_LEN + s0 + tx * 4;
        float4 og = { accg[i][0], accg[i][1], accg[i][2], accg[i][3] };
        float4 oh = { acch[i][0], acch[i][1], acch[i][2], acch[i][3] };
        *(float4*)(sc_Sg + off) = og;
        *(float4*)(sc_Sh + off) = oh;
    }
}

// ---------------- row softmax (in place), row length 1024 ------------------
__global__ __launch_bounds__(256) void softmax_rows(float* __restrict__ S)
{
    __shared__ float red[8];
    size_t base = (size_t)blockIdx.x * T_LEN;
    int tid = threadIdx.x;
    float4 v = *(float4*)(S + base + tid * 4);
    float m = fmaxf(fmaxf(v.x, v.y), fmaxf(v.z, v.w));
#pragma unroll
    for (int o = 16; o > 0; o >>= 1) m = fmaxf(m, __shfl_xor_sync(0xffffffffu, m, o));
    if ((tid & 31) == 0) red[tid >> 5] = m;
    __syncthreads();
    float bm = red[0];
#pragma unroll
    for (int w = 1; w < 8; w++) bm = fmaxf(bm, red[w]);
    __syncthreads();
    float e0 = __expf(v.x - bm), e1 = __expf(v.y - bm);
    float e2 = __expf(v.z - bm), e3 = __expf(v.w - bm);
    float s = e0 + e1 + e2 + e3;
#pragma unroll
    for (int o = 16; o > 0; o >>= 1) s += __shfl_xor_sync(0xffffffffu, s, o);
    if ((tid & 31) == 0) red[tid >> 5] = s;
    __syncthreads();
    float tot = red[0] + red[1] + red[2] + red[3] + red[4] + red[5] + red[6] + red[7];
    float inv = 1.0f / tot;
    float4 o4 = { e0 * inv, e1 * inv, e2 * inv, e3 * inv };
    *(float4*)(S + base + tid * 4) = o4;
}

// ---------------- gumbel sample: softmax(scores + gumbel(u)) in place ------
__global__ __launch_bounds__(256) void sample_rows(float* __restrict__ S)
{
    __shared__ float red[8];
    size_t base = (size_t)blockIdx.x * T_LEN;
    int tid = threadIdx.x;
    float4 v = *(float4*)(S + base + tid * 4);
    uint32_t i0 = (uint32_t)base + (uint32_t)(tid * 4);
    float vals[4] = { v.x, v.y, v.z, v.w };
#pragma unroll
    for (int c = 0; c < 4; c++) {
        uint32_t y = jax_bits_partitionable_xor(i0 + (uint32_t)c);
        float u = __uint_as_float((y >> 9) | 0x3f800000u) - 1.0f;
        // noise = -log(-log(u + eps) + eps); inner log accurate (u near 1 cancels)
        float inner = -logf(u + 1e-20f) + 1e-20f;
        vals[c] += -__logf(inner);
    }
    float m = fmaxf(fmaxf(vals[0], vals[1]), fmaxf(vals[2], vals[3]));
#pragma unroll
    for (int o = 16; o > 0; o >>= 1) m = fmaxf(m, __shfl_xor_sync(0xffffffffu, m, o));
    if ((tid & 31) == 0) red[tid >> 5] = m;
    __syncthreads();
    float bm = red[0];
#pragma unroll
    for (int w = 1; w < 8; w++) bm = fmaxf(bm, red[w]);
    __syncthreads();
    float e[4];
    float s = 0.f;
#pragma unroll
    for (int c = 0; c < 4; c++) { e[c] = __expf(vals[c] - bm); s += e[c]; }
#pragma unroll
    for (int o = 16; o > 0; o >>= 1) s += __shfl_xor_sync(0xffffffffu, s, o);
    if ((tid & 31) == 0) red[tid >> 5] = s;
    __syncthreads();
    float tot = red[0] + red[1] + red[2] + red[3] + red[4] + red[5] + red[6] + red[7];
    float inv = 1.0f / tot;
    float4 o4 = { e[0] * inv, e[1] * inv, e[2] * inv, e[3] * inv };
    *(float4*)(S + base + tid * 4) = o4;
}

// ---------------- attn @ V, writes merged [T*B, E] layout ------------------
__global__ __launch_bounds__(256) void av_kernel(
    const float* __restrict__ P, const float* __restrict__ Vsrc,
    int ldv, int vcoloff, float* __restrict__ Out)
{
    __shared__ float Pt[64][65];   // [s][t]
    __shared__ float Vs[64][68];   // [s][j]
    const int t0 = blockIdx.x * 64;
    const int bh = blockIdx.y;
    const int b = bh >> 4, hh = bh & 15;
    const int tid = threadIdx.x;
    const int tx = tid & 15, ty = tid >> 4;

    float acc[4][4] = {};
    const float* Pb = P + (size_t)bh * T_LEN * T_LEN;

    for (int sk = 0; sk < T_LEN; sk += 64) {
#pragma unroll
        for (int r = 0; r < 4; r++) {
            int fi = tid + r * 256;
            int row = fi >> 4;
            int cq = (fi & 15) << 2;
            float4 p = *(const float4*)(Pb + (size_t)(t0 + row) * T_LEN + sk + cq);
            Pt[cq+0][row] = p.x; Pt[cq+1][row] = p.y; Pt[cq+2][row] = p.z; Pt[cq+3][row] = p.w;
            float4 vv = *(const float4*)(Vsrc + (size_t)((sk + row) * BATCH + b) * ldv
                                         + vcoloff + hh * HDIM + cq);
            *(float4*)&Vs[row][cq] = vv;
        }
        __syncthreads();
#pragma unroll 8
        for (int s = 0; s < 64; s++) {
            float p0 = Pt[s][ty*4+0], p1 = Pt[s][ty*4+1], p2 = Pt[s][ty*4+2], p3 = Pt[s][ty*4+3];
            float4 vv = *(const float4*)&Vs[s][tx * 4];
            acc[0][0] = fmaf(p0, vv.x, acc[0][0]); acc[0][1] = fmaf(p0, vv.y, acc[0][1]);
            acc[0][2] = fmaf(p0, vv.z, acc[0][2]); acc[0][3] = fmaf(p0, vv.w, acc[0][3]);
            acc[1][0] = fmaf(p1, vv.x, acc[1][0]); acc[1][1] = fmaf(p1, vv.y, acc[1][1]);
            acc[1][2] = fmaf(p1, vv.z, acc[1][2]); acc[1][3] = fmaf(p1, vv.w, acc[1][3]);
            acc[2][0] = fmaf(p2, vv.x, acc[2][0]); acc[2][1] = fmaf(p2, vv.y, acc[2][1]);
            acc[2][2] = fmaf(p2, vv.z, acc[2][2]); acc[2][3] = fmaf(p2, vv.w, acc[2][3]);
            acc[3][0] = fmaf(p3, vv.x, acc[3][0]); acc[3][1] = fmaf(p3, vv.y, acc[3][1]);
            acc[3][2] = fmaf(p3, vv.z, acc[3][2]); acc[3][3] = fmaf(p3, vv.w, acc[3][3]);
        }
        __syncthreads();
    }
#pragma unroll
    for (int i = 0; i < 4; i++) {
        float4 o = { acc[i][0], acc[i][1], acc[i][2], acc[i][3] };
        *(float4*)(Out + (size_t)((t0 + ty * 4 + i) * BATCH + b) * EMB + hh * HDIM + tx * 4) = o;
    }
}

// ---------------- launch ---------------------------------------------------
extern "C" void kernel_launch(void* const* d_in, const int* in_sizes, int n_in,
                              void* d_out, int out_size)
{
    (void)in_sizes; (void)n_in; (void)out_size;
    const float* g       = (const float*)d_in[0];
    const float* h       = (const float*)d_in[1];
    const float* g_in_w  = (const float*)d_in[2];
    const float* g_in_b  = (const float*)d_in[3];
    const float* h_in_w  = (const float*)d_in[4];
    const float* h_in_b  = (const float*)d_in[5];
    const float* g_out_w = (const float*)d_in[6];
    const float* g_out_b = (const float*)d_in[7];
    const float* h_out_w = (const float*)d_in[8];
    const float* h_out_b = (const float*)d_in[9];
    float* out = (float*)d_out;

    float *qkv, *kvh, *Sg, *Sh, *ag, *ah;
    cudaGetSymbolAddress((void**)&qkv, sc_qkv);
    cudaGetSymbolAddress((void**)&kvh, sc_kvh);
    cudaGetSymbolAddress((void**)&Sg,  sc_Sg);
    cudaGetSymbolAddress((void**)&Sh,  sc_Sh);
    cudaGetSymbolAddress((void**)&ag,  sc_ag);
    cudaGetSymbolAddress((void**)&ah,  sc_ah);

    dim3 blk(256);
    // input projections (q scaled by 1/8 in epilogue: cols < 1024 of g proj)
    sgemm_bias<<<dim3(3072 / 128, MROWS / 128), blk>>>(g, g_in_w, g_in_b, qkv, 3072, EMB, 1024);
    sgemm_bias<<<dim3(2048 / 128, MROWS / 128), blk>>>(h, h_in_w, h_in_b, kvh, 2048, EMB, 0);
    // dual scores
    scores_kernel<<<dim3(16, 16, 32), blk>>>();
    // softmax / gumbel sample (in place)
    softmax_rows<<<BH * T_LEN, 256>>>(Sg);
    sample_rows<<<BH * T_LEN, 256>>>(Sh);
    // attention @ V  (gv at col 2048 of qkv; hv at col 1024 of kvh)
    av_kernel<<<dim3(16, 32), blk>>>(Sg, qkv, 3072, 2048, ag);
    av_kernel<<<dim3(16, 32), blk>>>(Sh, kvh, 2048, 1024, ah);
    // output projections straight into d_out (g first, h second)
    sgemm_bias<<<dim3(1024 / 128, MROWS / 128), blk>>>(ag, g_out_w, g_out_b, out,               1024, EMB, 0);
    sgemm_bias<<<dim3(1024 / 128, MROWS / 128), blk>>>(ah, h_out_w, h_out_b, out + MROWS * EMB, 1024, EMB, 0);
}

// round 11
// speedup vs baseline: 1.0174x; 1.0174x over previous
#include <cuda_runtime.h>
#include <cstdint>
#include <math_constants.h>

#define T_LEN 1024
#define BATCH 2
#define EMB 1024
#define HEADS 16
#define HDIM 64
#define MROWS (T_LEN * BATCH)   // 2048
#define BH (BATCH * HEADS)      // 32

// ---------------- scratch (device globals; no allocation) ----------------
__device__ float sc_qkv[MROWS * 3 * EMB];   // g-stream: q | gk | gv   (2048 x 3072)
__device__ float sc_kvh[MROWS * 2 * EMB];   // h-stream: hk | hv       (2048 x 2048)
__device__ float sc_ag[MROWS * EMB];        // merged g attention out [T*B, E]
__device__ float sc_ah[MROWS * EMB];        // merged h attention out

// ---------------- threefry2x32 (JAX, key = (0, 42)) -----------------------
// ks0 = 0, ks1 = 42, ks2 = 0x1BD11BDA ^ 0 ^ 42 = 0x1BD11BF0
static __device__ __forceinline__ uint2 threefry2x32_both(uint32_t c0, uint32_t c1) {
    const uint32_t ks1 = 42u;
    const uint32_t ks2 = 0x1BD11BF0u;
    uint32_t x0 = c0;            // + ks0 (=0)
    uint32_t x1 = c1 + ks1;
#define TF_R(r) { x0 += x1; x1 = __funnelshift_l(x1, x1, (r)); x1 ^= x0; }
    TF_R(13) TF_R(15) TF_R(26) TF_R(6)   x0 += ks1; x1 += ks2 + 1u;
    TF_R(17) TF_R(29) TF_R(16) TF_R(24)  x0 += ks2; x1 += 0u  + 2u;
    TF_R(13) TF_R(15) TF_R(26) TF_R(6)   x0 += 0u;  x1 += ks1 + 3u;
    TF_R(17) TF_R(29) TF_R(16) TF_R(24)  x0 += ks1; x1 += ks2 + 4u;
    TF_R(13) TF_R(15) TF_R(26) TF_R(6)   x0 += ks2; x1 += 0u  + 5u;
#undef TF_R
    return make_uint2(x0, x1);
}

// JAX partitionable mode: counts (0, i); 32-bit output = w0 ^ w1. (VERIFIED R10)
static __device__ __forceinline__ uint32_t jax_bits(uint32_t idx) {
    uint2 w = threefry2x32_both(0u, idx);
    return w.x ^ w.y;
}

// gumbel noise exactly as the passing sample_rows did it
static __device__ __forceinline__ float gumbel_noise(uint32_t idx) {
    uint32_t y = jax_bits(idx);
    float u = __uint_as_float((y >> 9) | 0x3f800000u) - 1.0f;
    float inner = -logf(u + 1e-20f) + 1e-20f;
    return -__logf(inner);
}

// ---------------- register-tiled SGEMM: C[M,N] = A[M,K] @ W[N,K]^T + bias ---
// epilogue: columns n < scale_cols multiplied by 0.125 (q * d^-0.5)
__global__ __launch_bounds__(256, 2) void sgemm_bias(
    const float* __restrict__ A, const float* __restrict__ W,
    const float* __restrict__ bias, float* __restrict__ C,
    int N, int K, int scale_cols)
{
    __shared__ float As[16][132];
    __shared__ float Bs[16][132];
    const int bm = blockIdx.y * 128;
    const int bn = blockIdx.x * 128;
    const int tid = threadIdx.x;
    const int tx = tid & 15, ty = tid >> 4;

    float acc[8][8];
#pragma unroll
    for (int i = 0; i < 8; i++)
#pragma unroll
        for (int j = 0; j < 8; j++) acc[i][j] = 0.f;

    const float* Ab = A + (size_t)bm * K;
    const float* Wb = W + (size_t)bn * K;

    for (int k0 = 0; k0 < K; k0 += 16) {
#pragma unroll
        for (int r = 0; r < 2; r++) {
            int idx = tid + r * 256;       // 0..511
            int row = idx >> 2;            // 0..127
            int kq  = (idx & 3) << 2;      // 0,4,8,12
            float4 va = *(const float4*)(Ab + (size_t)row * K + k0 + kq);
            As[kq+0][row] = va.x; As[kq+1][row] = va.y;
            As[kq+2][row] = va.z; As[kq+3][row] = va.w;
            float4 vb = *(const float4*)(Wb + (size_t)row * K + k0 + kq);
            Bs[kq+0][row] = vb.x; Bs[kq+1][row] = vb.y;
            Bs[kq+2][row] = vb.z; Bs[kq+3][row] = vb.w;
        }
        __syncthreads();
#pragma unroll
        for (int k = 0; k < 16; k++) {
            float ra[8], rb[8];
            *(float4*)(ra)     = *(const float4*)&As[k][ty * 8];
            *(float4*)(ra + 4) = *(const float4*)&As[k][ty * 8 + 4];
            *(float4*)(rb)     = *(const float4*)&Bs[k][tx * 8];
            *(float4*)(rb + 4) = *(const float4*)&Bs[k][tx * 8 + 4];
#pragma unroll
            for (int i = 0; i < 8; i++)
#pragma unroll
                for (int j = 0; j < 8; j++)
                    acc[i][j] = fmaf(ra[i], rb[j], acc[i][j]);
        }
        __syncthreads();
    }
#pragma unroll
    for (int i = 0; i < 8; i++) {
        int m = bm + ty * 8 + i;
#pragma unroll
        for (int j = 0; j < 8; j += 4) {
            int n = bn + tx * 8 + j;
            float4 o;
            o.x = acc[i][j+0] + bias[n+0];
            o.y = acc[i][j+1] + bias[n+1];
            o.z = acc[i][j+2] + bias[n+2];
            o.w = acc[i][j+3] + bias[n+3];
            if (n < scale_cols) { o.x *= 0.125f; o.y *= 0.125f; o.z *= 0.125f; o.w *= 0.125f; }
            *(float4*)(C + (size_t)m * N + n) = o;
        }
    }
}

// ---------------- fused flash attention: scores + (gumbel) softmax + P@V ---
// One block per (t-tile of 64, bh). Q from sc_qkv (col hh*64, ld 3072).
// K/V from KVsrc at column offsets koff/voff, leading dim ldkv.
// Online softmax, optional gumbel noise on scores. Output merged [T*B, E].
template<int DO_GUMBEL>
__global__ __launch_bounds__(256) void flash_kernel(
    const float* __restrict__ KVsrc, int ldkv, int koff, int voff,
    float* __restrict__ Out)
{
    __shared__ float Qs[64][65];   // [j][t]
    __shared__ float Ks[64][65];   // [j][s]
    __shared__ float Vs[64][68];   // [s][j]
    __shared__ float Pt[64][65];   // [s][t]

    const int t0 = blockIdx.x * 64;
    const int bh = blockIdx.y;
    const int b = bh >> 4, hh = bh & 15;
    const int col = hh * HDIM;
    const int tid = threadIdx.x;
    const int tx = tid & 15, ty = tid >> 4;

    // load Q tile [64 t x 64 j] -> Qs[j][t]
#pragma unroll
    for (int r = 0; r < 4; r++) {
        int fi = tid + r * 256;
        int row = fi >> 4;
        int jq = (fi & 15) << 2;
        float4 q = *(const float4*)(sc_qkv + (size_t)((t0 + row) * BATCH + b) * 3072 + col + jq);
        Qs[jq+0][row] = q.x; Qs[jq+1][row] = q.y; Qs[jq+2][row] = q.z; Qs[jq+3][row] = q.w;
    }

    float acc[4][4] = {};
    float m_i[4] = { -CUDART_INF_F, -CUDART_INF_F, -CUDART_INF_F, -CUDART_INF_F };
    float l_i[4] = {};

    for (int sk = 0; sk < T_LEN; sk += 64) {
        __syncthreads();   // previous iter's readers of Ks/Vs done
        // load K tile -> Ks[j][s], V tile -> Vs[s][j]
#pragma unroll
        for (int r = 0; r < 4; r++) {
            int fi = tid + r * 256;
            int row = fi >> 4;
            int jq = (fi & 15) << 2;
            const float* src = KVsrc + (size_t)((sk + row) * BATCH + b) * ldkv;
            float4 kk = *(const float4*)(src + koff + col + jq);
            Ks[jq+0][row] = kk.x; Ks[jq+1][row] = kk.y; Ks[jq+2][row] = kk.z; Ks[jq+3][row] = kk.w;
            float4 vv = *(const float4*)(src + voff + col + jq);
            *(float4*)&Vs[row][jq] = vv;
        }
        __syncthreads();

        // S tile 4x4 per thread: rows t0+ty*4+i, cols sk+tx*4+c
        float s4[4][4] = {};
#pragma unroll 8
        for (int j = 0; j < 64; j++) {
            float q0 = Qs[j][ty*4+0], q1 = Qs[j][ty*4+1], q2 = Qs[j][ty*4+2], q3 = Qs[j][ty*4+3];
            float k0 = Ks[j][tx*4+0], k1 = Ks[j][tx*4+1], k2 = Ks[j][tx*4+2], k3 = Ks[j][tx*4+3];
            s4[0][0] = fmaf(q0,k0,s4[0][0]); s4[0][1] = fmaf(q0,k1,s4[0][1]);
            s4[0][2] = fmaf(q0,k2,s4[0][2]); s4[0][3] = fmaf(q0,k3,s4[0][3]);
            s4[1][0] = fmaf(q1,k0,s4[1][0]); s4[1][1] = fmaf(q1,k1,s4[1][1]);
            s4[1][2] = fmaf(q1,k2,s4[1][2]); s4[1][3] = fmaf(q1,k3,s4[1][3]);
            s4[2][0] = fmaf(q2,k0,s4[2][0]); s4[2][1] = fmaf(q2,k1,s4[2][1]);
            s4[2][2] = fmaf(q2,k2,s4[2][2]); s4[2][3] = fmaf(q2,k3,s4[2][3]);
            s4[3][0] = fmaf(q3,k0,s4[3][0]); s4[3][1] = fmaf(q3,k1,s4[3][1]);
            s4[3][2] = fmaf(q3,k2,s4[3][2]); s4[3][3] = fmaf(q3,k3,s4[3][3]);
        }

        if (DO_GUMBEL) {
#pragma unroll
            for (int i = 0; i < 4; i++) {
                uint32_t rowbase = ((uint32_t)bh << 20) + ((uint32_t)(t0 + ty*4 + i) << 10)
                                 + (uint32_t)(sk + tx*4);
#pragma unroll
                for (int c = 0; c < 4; c++)
                    s4[i][c] += gumbel_noise(rowbase + (uint32_t)c);
            }
        }

        // online softmax update (row reduction across the 16 tx lanes)
#pragma unroll
        for (int i = 0; i < 4; i++) {
            float mx = fmaxf(fmaxf(s4[i][0], s4[i][1]), fmaxf(s4[i][2], s4[i][3]));
#pragma unroll
            for (int o = 1; o < 16; o <<= 1)
                mx = fmaxf(mx, __shfl_xor_sync(0xffffffffu, mx, o));
            float mnew = fmaxf(m_i[i], mx);
            float scale = __expf(m_i[i] - mnew);
            float rs = 0.f;
#pragma unroll
            for (int c = 0; c < 4; c++) {
                float p = __expf(s4[i][c] - mnew);
                s4[i][c] = p;
                rs += p;
            }
#pragma unroll
            for (int o = 1; o < 16; o <<= 1)
                rs += __shfl_xor_sync(0xffffffffu, rs, o);
            l_i[i] = l_i[i] * scale + rs;
            m_i[i] = mnew;
#pragma unroll
            for (int c = 0; c < 4; c++) acc[i][c] *= scale;
        }

        // share P across the row: Pt[s][t]
#pragma unroll
        for (int i = 0; i < 4; i++)
#pragma unroll
            for (int c = 0; c < 4; c++)
                Pt[tx*4+c][ty*4+i] = s4[i][c];
        __syncthreads();

        // acc += P @ V
#pragma unroll 8
        for (int s = 0; s < 64; s++) {
            float p0 = Pt[s][ty*4+0], p1 = Pt[s][ty*4+1], p2 = Pt[s][ty*4+2], p3 = Pt[s][ty*4+3];
            float4 vv = *(const float4*)&Vs[s][tx * 4];
            acc[0][0] = fmaf(p0, vv.x, acc[0][0]); acc[0][1] = fmaf(p0, vv.y, acc[0][1]);
            acc[0][2] = fmaf(p0, vv.z, acc[0][2]); acc[0][3] = fmaf(p0, vv.w, acc[0][3]);
            acc[1][0] = fmaf(p1, vv.x, acc[1][0]); acc[1][1] = fmaf(p1, vv.y, acc[1][1]);
            acc[1][2] = fmaf(p1, vv.z, acc[1][2]); acc[1][3] = fmaf(p1, vv.w, acc[1][3]);
            acc[2][0] = fmaf(p2, vv.x, acc[2][0]); acc[2][1] = fmaf(p2, vv.y, acc[2][1]);
            acc[2][2] = fmaf(p2, vv.z, acc[2][2]); acc[2][3] = fmaf(p2, vv.w, acc[2][3]);
            acc[3][0] = fmaf(p3, vv.x, acc[3][0]); acc[3][1] = fmaf(p3, vv.y, acc[3][1]);
            acc[3][2] = fmaf(p3, vv.z, acc[3][2]); acc[3][3] = fmaf(p3, vv.w, acc[3][3]);
        }
    }

    // normalize and write merged [T*B, E]
#pragma unroll
    for (int i = 0; i < 4; i++) {
        float inv = 1.0f / l_i[i];
        float4 o = { acc[i][0] * inv, acc[i][1] * inv, acc[i][2] * inv, acc[i][3] * inv };
        *(float4*)(Out + (size_t)((t0 + ty * 4 + i) * BATCH + b) * EMB + col + tx * 4) = o;
    }
}

// ---------------- launch ---------------------------------------------------
extern "C" void kernel_launch(void* const* d_in, const int* in_sizes, int n_in,
                              void* d_out, int out_size)
{
    (void)in_sizes; (void)n_in; (void)out_size;
    const float* g       = (const float*)d_in[0];
    const float* h       = (const float*)d_in[1];
    const float* g_in_w  = (const float*)d_in[2];
    const float* g_in_b  = (const float*)d_in[3];
    const float* h_in_w  = (const float*)d_in[4];
    const float* h_in_b  = (const float*)d_in[5];
    const float* g_out_w = (const float*)d_in[6];
    const float* g_out_b = (const float*)d_in[7];
    const float* h_out_w = (const float*)d_in[8];
    const float* h_out_b = (const float*)d_in[9];
    float* out = (float*)d_out;

    float *qkv, *kvh, *ag, *ah;
    cudaGetSymbolAddress((void**)&qkv, sc_qkv);
    cudaGetSymbolAddress((void**)&kvh, sc_kvh);
    cudaGetSymbolAddress((void**)&ag,  sc_ag);
    cudaGetSymbolAddress((void**)&ah,  sc_ah);

    dim3 blk(256);
    // input projections (q scaled by 1/8 in epilogue: cols < 1024 of g proj)
    sgemm_bias<<<dim3(3072 / 128, MROWS / 128), blk>>>(g, g_in_w, g_in_b, qkv, 3072, EMB, 1024);
    sgemm_bias<<<dim3(2048 / 128, MROWS / 128), blk>>>(h, h_in_w, h_in_b, kvh, 2048, EMB, 0);
    // fused attention: scores + softmax(+gumbel) + P@V, merged output layout
    flash_kernel<0><<<dim3(16, 32), blk>>>(qkv, 3072, 1024, 2048, ag);
    flash_kernel<1><<<dim3(16, 32), blk>>>(kvh, 2048, 0,    1024, ah);
    // output projections straight into d_out (g first, h second)
    sgemm_bias<<<dim3(1024 / 128, MROWS / 128), blk>>>(ag, g_out_w, g_out_b, out,               1024, EMB, 0);
    sgemm_bias<<<dim3(1024 / 128, MROWS / 128), blk>>>(ah, h_out_w, h_out_b, out + MROWS * EMB, 1024, EMB, 0);
}

// round 12
// speedup vs baseline: 1.5401x; 1.5137x over previous
#include <cuda_runtime.h>
#include <cstdint>
#include <math_constants.h>

#define T_LEN 1024
#define BATCH 2
#define EMB 1024
#define HEADS 16
#define HDIM 64
#define MROWS (T_LEN * BATCH)   // 2048
#define BH (BATCH * HEADS)      // 32

// ---------------- scratch (device globals; no allocation) ----------------
__device__ float sc_qkv[MROWS * 3 * EMB];   // g-stream: q | gk | gv   (2048 x 3072)
__device__ float sc_kvh[MROWS * 2 * EMB];   // h-stream: hk | hv       (2048 x 2048)
__device__ float sc_ag[MROWS * EMB];        // merged g attention out [T*B, E]
__device__ float sc_ah[MROWS * EMB];        // merged h attention out

// ---------------- threefry2x32 (JAX, key = (0, 42)) -----------------------
static __device__ __forceinline__ uint2 threefry2x32_both(uint32_t c0, uint32_t c1) {
    const uint32_t ks1 = 42u;
    const uint32_t ks2 = 0x1BD11BF0u;
    uint32_t x0 = c0;
    uint32_t x1 = c1 + ks1;
#define TF_R(r) { x0 += x1; x1 = __funnelshift_l(x1, x1, (r)); x1 ^= x0; }
    TF_R(13) TF_R(15) TF_R(26) TF_R(6)   x0 += ks1; x1 += ks2 + 1u;
    TF_R(17) TF_R(29) TF_R(16) TF_R(24)  x0 += ks2; x1 += 0u  + 2u;
    TF_R(13) TF_R(15) TF_R(26) TF_R(6)   x0 += 0u;  x1 += ks1 + 3u;
    TF_R(17) TF_R(29) TF_R(16) TF_R(24)  x0 += ks1; x1 += ks2 + 4u;
    TF_R(13) TF_R(15) TF_R(26) TF_R(6)   x0 += ks2; x1 += 0u  + 5u;
#undef TF_R
    return make_uint2(x0, x1);
}

// JAX partitionable mode: counts (0, i); output = w0 ^ w1. (VERIFIED R10)
static __device__ __forceinline__ uint32_t jax_bits(uint32_t idx) {
    uint2 w = threefry2x32_both(0u, idx);
    return w.x ^ w.y;
}

static __device__ __forceinline__ float gumbel_noise(uint32_t idx) {
    uint32_t y = jax_bits(idx);
    float u = __uint_as_float((y >> 9) | 0x3f800000u) - 1.0f;
    float inner = -logf(u + 1e-20f) + 1e-20f;
    return -__logf(inner);
}

// ---------------- tf32 helpers ---------------------------------------------
static __device__ __forceinline__ uint32_t f2tf32(float f) {
    uint32_t r;
    asm("cvt.rna.tf32.f32 %0, %1;" : "=r"(r) : "f"(f));
    return r;
}

// ---------------- tf32 tensor-core GEMM: C = A[M,K] @ W[N,K]^T + bias ------
// 128x128 block tile, BK=32, 8 warps (2M x 4N), warp tile 64x32,
// mma.sync.m16n8k8 tf32, fp32 accumulate. Register-staged global prefetch.
// epilogue: columns n < scale_cols multiplied by 0.125 (q * d^-0.5)
__global__ __launch_bounds__(256) void tf32_gemm_bias(
    const float* __restrict__ A, const float* __restrict__ W,
    const float* __restrict__ bias, float* __restrict__ C,
    int N, int K, int scale_cols)
{
    __shared__ uint32_t As[128 * 36];   // [m][k], pad 36 -> conflict-free frags
    __shared__ uint32_t Bs[128 * 36];   // [n][k]
    const int bm = blockIdx.y * 128;
    const int bn = blockIdx.x * 128;
    const int tid = threadIdx.x;
    const int lane = tid & 31, warp = tid >> 5;
    const int warpM = warp & 1, warpN = warp >> 1;   // 2 x 4
    const int mbase = warpM * 64, nbase = warpN * 32;
    const int g = lane >> 2, tg = lane & 3;

    float acc[4][4][4];
#pragma unroll
    for (int mt = 0; mt < 4; mt++)
#pragma unroll
        for (int nt = 0; nt < 4; nt++)
#pragma unroll
            for (int c = 0; c < 4; c++) acc[mt][nt][c] = 0.f;

    const float* Ab = A + (size_t)bm * K;
    const float* Wb = W + (size_t)bn * K;

    float4 stA[4], stB[4];
    // prologue: load first k-tile
#pragma unroll
    for (int i = 0; i < 4; i++) {
        int idx = i * 256 + tid;              // 0..1023
        int row = idx >> 3, col = (idx & 7) << 2;
        stA[i] = *(const float4*)(Ab + (size_t)row * K + col);
        stB[i] = *(const float4*)(Wb + (size_t)row * K + col);
    }
#pragma unroll
    for (int i = 0; i < 4; i++) {
        int idx = i * 256 + tid;
        int row = idx >> 3, col = (idx & 7) << 2;
        uint4 a4 = { f2tf32(stA[i].x), f2tf32(stA[i].y), f2tf32(stA[i].z), f2tf32(stA[i].w) };
        *(uint4*)&As[row * 36 + col] = a4;
        uint4 b4 = { f2tf32(stB[i].x), f2tf32(stB[i].y), f2tf32(stB[i].z), f2tf32(stB[i].w) };
        *(uint4*)&Bs[row * 36 + col] = b4;
    }
    __syncthreads();

    for (int k0 = 0; k0 < K; k0 += 32) {
        const bool has_next = (k0 + 32) < K;
        if (has_next) {
#pragma unroll
            for (int i = 0; i < 4; i++) {
                int idx = i * 256 + tid;
                int row = idx >> 3, col = (idx & 7) << 2;
                stA[i] = *(const float4*)(Ab + (size_t)row * K + k0 + 32 + col);
                stB[i] = *(const float4*)(Wb + (size_t)row * K + k0 + 32 + col);
            }
        }
#pragma unroll
        for (int ks = 0; ks < 32; ks += 8) {
            uint32_t af[4][4], bf[4][2];
#pragma unroll
            for (int mt = 0; mt < 4; mt++) {
                int r0 = (mbase + mt * 16 + g) * 36 + ks + tg;
                af[mt][0] = As[r0];
                af[mt][1] = As[r0 + 8 * 36];
                af[mt][2] = As[r0 + 4];
                af[mt][3] = As[r0 + 8 * 36 + 4];
            }
#pragma unroll
            for (int nt = 0; nt < 4; nt++) {
                int r0 = (nbase + nt * 8 + g) * 36 + ks + tg;
                bf[nt][0] = Bs[r0];
                bf[nt][1] = Bs[r0 + 4];
            }
#pragma unroll
            for (int mt = 0; mt < 4; mt++)
#pragma unroll
                for (int nt = 0; nt < 4; nt++)
                    asm volatile(
                        "mma.sync.aligned.m16n8k8.row.col.f32.tf32.tf32.f32 "
                        "{%0,%1,%2,%3}, {%4,%5,%6,%7}, {%8,%9}, {%0,%1,%2,%3};"
                        : "+f"(acc[mt][nt][0]), "+f"(acc[mt][nt][1]),
                          "+f"(acc[mt][nt][2]), "+f"(acc[mt][nt][3])
                        : "r"(af[mt][0]), "r"(af[mt][1]), "r"(af[mt][2]), "r"(af[mt][3]),
                          "r"(bf[nt][0]), "r"(bf[nt][1]));
        }
        if (has_next) {
            __syncthreads();
#pragma unroll
            for (int i = 0; i < 4; i++) {
                int idx = i * 256 + tid;
                int row = idx >> 3, col = (idx & 7) << 2;
                uint4 a4 = { f2tf32(stA[i].x), f2tf32(stA[i].y), f2tf32(stA[i].z), f2tf32(stA[i].w) };
                *(uint4*)&As[row * 36 + col] = a4;
                uint4 b4 = { f2tf32(stB[i].x), f2tf32(stB[i].y), f2tf32(stB[i].z), f2tf32(stB[i].w) };
                *(uint4*)&Bs[row * 36 + col] = b4;
            }
            __syncthreads();
        }
    }

    // epilogue: c0,c1 at (row, col..col+1), c2,c3 at (row+8, ...)
#pragma unroll
    for (int mt = 0; mt < 4; mt++) {
        int row = bm + mbase + mt * 16 + g;
#pragma unroll
        for (int nt = 0; nt < 4; nt++) {
            int col = bn + nbase + nt * 8 + 2 * tg;
            float bx = bias[col], by = bias[col + 1];
            float2 v0 = { acc[mt][nt][0] + bx, acc[mt][nt][1] + by };
            float2 v1 = { acc[mt][nt][2] + bx, acc[mt][nt][3] + by };
            if (col < scale_cols) {
                v0.x *= 0.125f; v0.y *= 0.125f; v1.x *= 0.125f; v1.y *= 0.125f;
            }
            *(float2*)(C + (size_t)row * N + col) = v0;
            *(float2*)(C + (size_t)(row + 8) * N + col) = v1;
        }
    }
}

// ---------------- fused flash attention: scores + (gumbel) softmax + P@V ---
template<int DO_GUMBEL>
__global__ __launch_bounds__(256) void flash_kernel(
    const float* __restrict__ KVsrc, int ldkv, int koff, int voff,
    float* __restrict__ Out)
{
    __shared__ float Qs[64][65];   // [j][t]
    __shared__ float Ks[64][65];   // [j][s]
    __shared__ float Vs[64][68];   // [s][j]
    __shared__ float Pt[64][65];   // [s][t]

    const int t0 = blockIdx.x * 64;
    const int bh = blockIdx.y;
    const int b = bh >> 4, hh = bh & 15;
    const int col = hh * HDIM;
    const int tid = threadIdx.x;
    const int tx = tid & 15, ty = tid >> 4;

#pragma unroll
    for (int r = 0; r < 4; r++) {
        int fi = tid + r * 256;
        int row = fi >> 4;
        int jq = (fi & 15) << 2;
        float4 q = *(const float4*)(sc_qkv + (size_t)((t0 + row) * BATCH + b) * 3072 + col + jq);
        Qs[jq+0][row] = q.x; Qs[jq+1][row] = q.y; Qs[jq+2][row] = q.z; Qs[jq+3][row] = q.w;
    }

    float acc[4][4] = {};
    float m_i[4] = { -CUDART_INF_F, -CUDART_INF_F, -CUDART_INF_F, -CUDART_INF_F };
    float l_i[4] = {};

    for (int sk = 0; sk < T_LEN; sk += 64) {
        __syncthreads();
#pragma unroll
        for (int r = 0; r < 4; r++) {
            int fi = tid + r * 256;
            int row = fi >> 4;
            int jq = (fi & 15) << 2;
            const float* src = KVsrc + (size_t)((sk + row) * BATCH + b) * ldkv;
            float4 kk = *(const float4*)(src + koff + col + jq);
            Ks[jq+0][row] = kk.x; Ks[jq+1][row] = kk.y; Ks[jq+2][row] = kk.z; Ks[jq+3][row] = kk.w;
            float4 vv = *(const float4*)(src + voff + col + jq);
            *(float4*)&Vs[row][jq] = vv;
        }
        __syncthreads();

        float s4[4][4] = {};
#pragma unroll 8
        for (int j = 0; j < 64; j++) {
            float q0 = Qs[j][ty*4+0], q1 = Qs[j][ty*4+1], q2 = Qs[j][ty*4+2], q3 = Qs[j][ty*4+3];
            float k0 = Ks[j][tx*4+0], k1 = Ks[j][tx*4+1], k2 = Ks[j][tx*4+2], k3 = Ks[j][tx*4+3];
            s4[0][0] = fmaf(q0,k0,s4[0][0]); s4[0][1] = fmaf(q0,k1,s4[0][1]);
            s4[0][2] = fmaf(q0,k2,s4[0][2]); s4[0][3] = fmaf(q0,k3,s4[0][3]);
            s4[1][0] = fmaf(q1,k0,s4[1][0]); s4[1][1] = fmaf(q1,k1,s4[1][1]);
            s4[1][2] = fmaf(q1,k2,s4[1][2]); s4[1][3] = fmaf(q1,k3,s4[1][3]);
            s4[2][0] = fmaf(q2,k0,s4[2][0]); s4[2][1] = fmaf(q2,k1,s4[2][1]);
            s4[2][2] = fmaf(q2,k2,s4[2][2]); s4[2][3] = fmaf(q2,k3,s4[2][3]);
            s4[3][0] = fmaf(q3,k0,s4[3][0]); s4[3][1] = fmaf(q3,k1,s4[3][1]);
            s4[3][2] = fmaf(q3,k2,s4[3][2]); s4[3][3] = fmaf(q3,k3,s4[3][3]);
        }

        if (DO_GUMBEL) {
#pragma unroll
            for (int i = 0; i < 4; i++) {
                uint32_t rowbase = ((uint32_t)bh << 20) + ((uint32_t)(t0 + ty*4 + i) << 10)
                                 + (uint32_t)(sk + tx*4);
#pragma unroll
                for (int c = 0; c < 4; c++)
                    s4[i][c] += gumbel_noise(rowbase + (uint32_t)c);
            }
        }

#pragma unroll
        for (int i = 0; i < 4; i++) {
            float mx = fmaxf(fmaxf(s4[i][0], s4[i][1]), fmaxf(s4[i][2], s4[i][3]));
#pragma unroll
            for (int o = 1; o < 16; o <<= 1)
                mx = fmaxf(mx, __shfl_xor_sync(0xffffffffu, mx, o));
            float mnew = fmaxf(m_i[i], mx);
            float scale = __expf(m_i[i] - mnew);
            float rs = 0.f;
#pragma unroll
            for (int c = 0; c < 4; c++) {
                float p = __expf(s4[i][c] - mnew);
                s4[i][c] = p;
                rs += p;
            }
#pragma unroll
            for (int o = 1; o < 16; o <<= 1)
                rs += __shfl_xor_sync(0xffffffffu, rs, o);
            l_i[i] = l_i[i] * scale + rs;
            m_i[i] = mnew;
#pragma unroll
            for (int c = 0; c < 4; c++) acc[i][c] *= scale;
        }

#pragma unroll
        for (int i = 0; i < 4; i++)
#pragma unroll
            for (int c = 0; c < 4; c++)
                Pt[tx*4+c][ty*4+i] = s4[i][c];
        __syncthreads();

#pragma unroll 8
        for (int s = 0; s < 64; s++) {
            float p0 = Pt[s][ty*4+0], p1 = Pt[s][ty*4+1], p2 = Pt[s][ty*4+2], p3 = Pt[s][ty*4+3];
            float4 vv = *(const float4*)&Vs[s][tx * 4];
            acc[0][0] = fmaf(p0, vv.x, acc[0][0]); acc[0][1] = fmaf(p0, vv.y, acc[0][1]);
            acc[0][2] = fmaf(p0, vv.z, acc[0][2]); acc[0][3] = fmaf(p0, vv.w, acc[0][3]);
            acc[1][0] = fmaf(p1, vv.x, acc[1][0]); acc[1][1] = fmaf(p1, vv.y, acc[1][1]);
            acc[1][2] = fmaf(p1, vv.z, acc[1][2]); acc[1][3] = fmaf(p1, vv.w, acc[1][3]);
            acc[2][0] = fmaf(p2, vv.x, acc[2][0]); acc[2][1] = fmaf(p2, vv.y, acc[2][1]);
            acc[2][2] = fmaf(p2, vv.z, acc[2][2]); acc[2][3] = fmaf(p2, vv.w, acc[2][3]);
            acc[3][0] = fmaf(p3, vv.x, acc[3][0]); acc[3][1] = fmaf(p3, vv.y, acc[3][1]);
            acc[3][2] = fmaf(p3, vv.z, acc[3][2]); acc[3][3] = fmaf(p3, vv.w, acc[3][3]);
        }
    }

#pragma unroll
    for (int i = 0; i < 4; i++) {
        float inv = 1.0f / l_i[i];
        float4 o = { acc[i][0] * inv, acc[i][1] * inv, acc[i][2] * inv, acc[i][3] * inv };
        *(float4*)(Out + (size_t)((t0 + ty * 4 + i) * BATCH + b) * EMB + col + tx * 4) = o;
    }
}

// ---------------- launch ---------------------------------------------------
extern "C" void kernel_launch(void* const* d_in, const int* in_sizes, int n_in,
                              void* d_out, int out_size)
{
    (void)in_sizes; (void)n_in; (void)out_size;
    const float* g       = (const float*)d_in[0];
    const float* h       = (const float*)d_in[1];
    const float* g_in_w  = (const float*)d_in[2];
    const float* g_in_b  = (const float*)d_in[3];
    const float* h_in_w  = (const float*)d_in[4];
    const float* h_in_b  = (const float*)d_in[5];
    const float* g_out_w = (const float*)d_in[6];
    const float* g_out_b = (const float*)d_in[7];
    const float* h_out_w = (const float*)d_in[8];
    const float* h_out_b = (const float*)d_in[9];
    float* out = (float*)d_out;

    float *qkv, *kvh, *ag, *ah;
    cudaGetSymbolAddress((void**)&qkv, sc_qkv);
    cudaGetSymbolAddress((void**)&kvh, sc_kvh);
    cudaGetSymbolAddress((void**)&ag,  sc_ag);
    cudaGetSymbolAddress((void**)&ah,  sc_ah);

    dim3 blk(256);
    // input projections on tensor cores (q scaled by 1/8: cols < 1024 of g proj)
    tf32_gemm_bias<<<dim3(3072 / 128, MROWS / 128), blk>>>(g, g_in_w, g_in_b, qkv, 3072, EMB, 1024);
    tf32_gemm_bias<<<dim3(2048 / 128, MROWS / 128), blk>>>(h, h_in_w, h_in_b, kvh, 2048, EMB, 0);
    // fused attention: scores + softmax(+gumbel) + P@V, merged output layout
    flash_kernel<0><<<dim3(16, 32), blk>>>(qkv, 3072, 1024, 2048, ag);
    flash_kernel<1><<<dim3(16, 32), blk>>>(kvh, 2048, 0,    1024, ah);
    // output projections straight into d_out (g first, h second)
    tf32_gemm_bias<<<dim3(1024 / 128, MROWS / 128), blk>>>(ag, g_out_w, g_out_b, out,               1024, EMB, 0);
    tf32_gemm_bias<<<dim3(1024 / 128, MROWS / 128), blk>>>(ah, h_out_w, h_out_b, out + MROWS * EMB, 1024, EMB, 0);
}

// round 13
// speedup vs baseline: 2.4501x; 1.5908x over previous
#include <cuda_runtime.h>
#include <cstdint>
#include <math_constants.h>

#define T_LEN 1024
#define BATCH 2
#define EMB 1024
#define HEADS 16
#define HDIM 64
#define MROWS (T_LEN * BATCH)   // 2048
#define BH (BATCH * HEADS)      // 32

// ---------------- scratch (device globals; no allocation) ----------------
__device__ float sc_qkv[MROWS * 3 * EMB];   // g-stream: q | gk | gv   (2048 x 3072)
__device__ float sc_kvh[MROWS * 2 * EMB];   // h-stream: hk | hv       (2048 x 2048)
__device__ float sc_ag[MROWS * EMB];        // merged g attention out [T*B, E]
__device__ float sc_ah[MROWS * EMB];        // merged h attention out

// ---------------- threefry2x32 (JAX, key = (0, 42)) -----------------------
static __device__ __forceinline__ uint2 threefry2x32_both(uint32_t c0, uint32_t c1) {
    const uint32_t ks1 = 42u;
    const uint32_t ks2 = 0x1BD11BF0u;
    uint32_t x0 = c0;
    uint32_t x1 = c1 + ks1;
#define TF_R(r) { x0 += x1; x1 = __funnelshift_l(x1, x1, (r)); x1 ^= x0; }
    TF_R(13) TF_R(15) TF_R(26) TF_R(6)   x0 += ks1; x1 += ks2 + 1u;
    TF_R(17) TF_R(29) TF_R(16) TF_R(24)  x0 += ks2; x1 += 0u  + 2u;
    TF_R(13) TF_R(15) TF_R(26) TF_R(6)   x0 += 0u;  x1 += ks1 + 3u;
    TF_R(17) TF_R(29) TF_R(16) TF_R(24)  x0 += ks1; x1 += ks2 + 4u;
    TF_R(13) TF_R(15) TF_R(26) TF_R(6)   x0 += ks2; x1 += 0u  + 5u;
#undef TF_R
    return make_uint2(x0, x1);
}

// JAX partitionable mode: counts (0, i); output = w0 ^ w1. (VERIFIED R10)
static __device__ __forceinline__ uint32_t jax_bits(uint32_t idx) {
    uint2 w = threefry2x32_both(0u, idx);
    return w.x ^ w.y;
}

static __device__ __forceinline__ float gumbel_noise(uint32_t idx) {
    uint32_t y = jax_bits(idx);
    float u = __uint_as_float((y >> 9) | 0x3f800000u) - 1.0f;
    float inner = -logf(u + 1e-20f) + 1e-20f;
    return -__logf(inner);
}

// ---------------- tf32 helpers ---------------------------------------------
static __device__ __forceinline__ uint32_t f2tf32(float f) {
    uint32_t r;
    asm("cvt.rna.tf32.f32 %0, %1;" : "=r"(r) : "f"(f));
    return r;
}

#define MMA_TF32(acc, a0, a1, a2, a3, b0, b1)                                  \
    asm volatile(                                                              \
        "mma.sync.aligned.m16n8k8.row.col.f32.tf32.tf32.f32 "                  \
        "{%0,%1,%2,%3}, {%4,%5,%6,%7}, {%8,%9}, {%0,%1,%2,%3};"                \
        : "+f"((acc)[0]), "+f"((acc)[1]), "+f"((acc)[2]), "+f"((acc)[3])       \
        : "r"(a0), "r"(a1), "r"(a2), "r"(a3), "r"(b0), "r"(b1))

// ---------------- tf32 tensor-core GEMM: C = A[M,K] @ W[N,K]^T + bias ------
// (verified R12) 128x128 block tile, BK=32, 8 warps, m16n8k8 tf32.
__global__ __launch_bounds__(256) void tf32_gemm_bias(
    const float* __restrict__ A, const float* __restrict__ W,
    const float* __restrict__ bias, float* __restrict__ C,
    int N, int K, int scale_cols)
{
    __shared__ uint32_t As[128 * 36];
    __shared__ uint32_t Bs[128 * 36];
    const int bm = blockIdx.y * 128;
    const int bn = blockIdx.x * 128;
    const int tid = threadIdx.x;
    const int lane = tid & 31, warp = tid >> 5;
    const int warpM = warp & 1, warpN = warp >> 1;
    const int mbase = warpM * 64, nbase = warpN * 32;
    const int g = lane >> 2, tg = lane & 3;

    float acc[4][4][4];
#pragma unroll
    for (int mt = 0; mt < 4; mt++)
#pragma unroll
        for (int nt = 0; nt < 4; nt++)
#pragma unroll
            for (int c = 0; c < 4; c++) acc[mt][nt][c] = 0.f;

    const float* Ab = A + (size_t)bm * K;
    const float* Wb = W + (size_t)bn * K;

    float4 stA[4], stB[4];
#pragma unroll
    for (int i = 0; i < 4; i++) {
        int idx = i * 256 + tid;
        int row = idx >> 3, c4 = (idx & 7) << 2;
        stA[i] = *(const float4*)(Ab + (size_t)row * K + c4);
        stB[i] = *(const float4*)(Wb + (size_t)row * K + c4);
    }
#pragma unroll
    for (int i = 0; i < 4; i++) {
        int idx = i * 256 + tid;
        int row = idx >> 3, c4 = (idx & 7) << 2;
        uint4 a4 = { f2tf32(stA[i].x), f2tf32(stA[i].y), f2tf32(stA[i].z), f2tf32(stA[i].w) };
        *(uint4*)&As[row * 36 + c4] = a4;
        uint4 b4 = { f2tf32(stB[i].x), f2tf32(stB[i].y), f2tf32(stB[i].z), f2tf32(stB[i].w) };
        *(uint4*)&Bs[row * 36 + c4] = b4;
    }
    __syncthreads();

    for (int k0 = 0; k0 < K; k0 += 32) {
        const bool has_next = (k0 + 32) < K;
        if (has_next) {
#pragma unroll
            for (int i = 0; i < 4; i++) {
                int idx = i * 256 + tid;
                int row = idx >> 3, c4 = (idx & 7) << 2;
                stA[i] = *(const float4*)(Ab + (size_t)row * K + k0 + 32 + c4);
                stB[i] = *(const float4*)(Wb + (size_t)row * K + k0 + 32 + c4);
            }
        }
#pragma unroll
        for (int ks = 0; ks < 32; ks += 8) {
            uint32_t af[4][4], bf[4][2];
#pragma unroll
            for (int mt = 0; mt < 4; mt++) {
                int r0 = (mbase + mt * 16 + g) * 36 + ks + tg;
                af[mt][0] = As[r0];
                af[mt][1] = As[r0 + 8 * 36];
                af[mt][2] = As[r0 + 4];
                af[mt][3] = As[r0 + 8 * 36 + 4];
            }
#pragma unroll
            for (int nt = 0; nt < 4; nt++) {
                int r0 = (nbase + nt * 8 + g) * 36 + ks + tg;
                bf[nt][0] = Bs[r0];
                bf[nt][1] = Bs[r0 + 4];
            }
#pragma unroll
            for (int mt = 0; mt < 4; mt++)
#pragma unroll
                for (int nt = 0; nt < 4; nt++)
                    MMA_TF32(acc[mt][nt], af[mt][0], af[mt][1], af[mt][2], af[mt][3],
                             bf[nt][0], bf[nt][1]);
        }
        if (has_next) {
            __syncthreads();
#pragma unroll
            for (int i = 0; i < 4; i++) {
                int idx = i * 256 + tid;
                int row = idx >> 3, c4 = (idx & 7) << 2;
                uint4 a4 = { f2tf32(stA[i].x), f2tf32(stA[i].y), f2tf32(stA[i].z), f2tf32(stA[i].w) };
                *(uint4*)&As[row * 36 + c4] = a4;
                uint4 b4 = { f2tf32(stB[i].x), f2tf32(stB[i].y), f2tf32(stB[i].z), f2tf32(stB[i].w) };
                *(uint4*)&Bs[row * 36 + c4] = b4;
            }
            __syncthreads();
        }
    }

#pragma unroll
    for (int mt = 0; mt < 4; mt++) {
        int row = bm + mbase + mt * 16 + g;
#pragma unroll
        for (int nt = 0; nt < 4; nt++) {
            int c0 = bn + nbase + nt * 8 + 2 * tg;
            float bx = bias[c0], by = bias[c0 + 1];
            float2 v0 = { acc[mt][nt][0] + bx, acc[mt][nt][1] + by };
            float2 v1 = { acc[mt][nt][2] + bx, acc[mt][nt][3] + by };
            if (c0 < scale_cols) {
                v0.x *= 0.125f; v0.y *= 0.125f; v1.x *= 0.125f; v1.y *= 0.125f;
            }
            *(float2*)(C + (size_t)row * N + c0) = v0;
            *(float2*)(C + (size_t)(row + 8) * N + c0) = v1;
        }
    }
}

// ---------------- tensor-core fused flash attention ------------------------
// BM=128 t-rows/block, 64 s-cols per iteration, 8 warps each m16 x n64.
// S = Q@K^T (tf32 mma) -> [+gumbel] online softmax on fragments ->
// P via smem (tf32) -> O += P@V (tf32 mma). Output merged [T*B, E].
#define FPAD 68
#define SM_Q  0                       // [128][68]
#define SM_K  (128 * FPAD)            // [64][68]
#define SM_V  (128 * FPAD + 64 * FPAD)
#define SM_P  (128 * FPAD + 2 * 64 * FPAD)
#define FLASH_SMEM_BYTES ((2 * 128 * FPAD + 2 * 64 * FPAD) * 4)

template<int DO_GUMBEL>
__global__ __launch_bounds__(256) void flash_mma(
    const float* __restrict__ KVsrc, int ldkv, int koff, int voff,
    float* __restrict__ Out)
{
    extern __shared__ uint32_t sm[];
    uint32_t* Qs = sm + SM_Q;
    uint32_t* Ks = sm + SM_K;
    uint32_t* Vs = sm + SM_V;
    uint32_t* Pt = sm + SM_P;

    const int t0 = blockIdx.x * 128;
    const int bh = blockIdx.y;
    const int b = bh >> 4, hh = bh & 15;
    const int col = hh * HDIM;
    const int tid = threadIdx.x;
    const int lane = tid & 31, warp = tid >> 5;
    const int g = lane >> 2, tg = lane & 3;
    const int m0 = warp * 16;

    // load Q tile [128 t][64 j] as tf32
#pragma unroll
    for (int r = 0; r < 8; r++) {
        int fi = r * 256 + tid;
        int row = fi >> 4, jq = (fi & 15) << 2;
        float4 q = *(const float4*)(sc_qkv + (size_t)((t0 + row) * BATCH + b) * 3072 + col + jq);
        uint4 u = { f2tf32(q.x), f2tf32(q.y), f2tf32(q.z), f2tf32(q.w) };
        *(uint4*)&Qs[row * FPAD + jq] = u;
    }

    float acc_o[8][4];
#pragma unroll
    for (int nf = 0; nf < 8; nf++)
#pragma unroll
        for (int c = 0; c < 4; c++) acc_o[nf][c] = 0.f;
    float mA = -CUDART_INF_F, mB = -CUDART_INF_F, lA = 0.f, lB = 0.f;

    for (int sk = 0; sk < T_LEN; sk += 64) {
        __syncthreads();   // previous PV readers of Ks/Vs/Pt done
#pragma unroll
        for (int r = 0; r < 4; r++) {
            int fi = r * 256 + tid;
            int row = fi >> 4, jq = (fi & 15) << 2;
            const float* src = KVsrc + (size_t)((sk + row) * BATCH + b) * ldkv;
            float4 kk = *(const float4*)(src + koff + col + jq);
            uint4 uk = { f2tf32(kk.x), f2tf32(kk.y), f2tf32(kk.z), f2tf32(kk.w) };
            *(uint4*)&Ks[row * FPAD + jq] = uk;
            float4 vv = *(const float4*)(src + voff + col + jq);
            uint4 uv = { f2tf32(vv.x), f2tf32(vv.y), f2tf32(vv.z), f2tf32(vv.w) };
            *(uint4*)&Vs[row * FPAD + jq] = uv;
        }
        __syncthreads();

        // S = Q @ K^T : warp rows [m0, m0+16), all 64 cols
        float acc_s[8][4];
#pragma unroll
        for (int nf = 0; nf < 8; nf++)
#pragma unroll
            for (int c = 0; c < 4; c++) acc_s[nf][c] = 0.f;
#pragma unroll
        for (int ks = 0; ks < 8; ks++) {
            uint32_t a0 = Qs[(m0 + g) * FPAD + ks * 8 + tg];
            uint32_t a1 = Qs[(m0 + g + 8) * FPAD + ks * 8 + tg];
            uint32_t a2 = Qs[(m0 + g) * FPAD + ks * 8 + tg + 4];
            uint32_t a3 = Qs[(m0 + g + 8) * FPAD + ks * 8 + tg + 4];
#pragma unroll
            for (int nf = 0; nf < 8; nf++) {
                uint32_t b0 = Ks[(nf * 8 + g) * FPAD + ks * 8 + tg];
                uint32_t b1 = Ks[(nf * 8 + g) * FPAD + ks * 8 + tg + 4];
                MMA_TF32(acc_s[nf], a0, a1, a2, a3, b0, b1);
            }
        }

        if (DO_GUMBEL) {
#pragma unroll
            for (int nf = 0; nf < 8; nf++) {
                uint32_t i00 = ((uint32_t)bh << 20) + ((uint32_t)(t0 + m0 + g) << 10)
                             + (uint32_t)(sk + nf * 8 + 2 * tg);
                acc_s[nf][0] += gumbel_noise(i00);
                acc_s[nf][1] += gumbel_noise(i00 + 1u);
                uint32_t i10 = i00 + (8u << 10);
                acc_s[nf][2] += gumbel_noise(i10);
                acc_s[nf][3] += gumbel_noise(i10 + 1u);
            }
        }

        // online softmax: rows (m0+g) [c0,c1] and (m0+g+8) [c2,c3],
        // full row lives in the 4-lane tg quad -> 2 shfls.
        float mxA = -CUDART_INF_F, mxB = -CUDART_INF_F;
#pragma unroll
        for (int nf = 0; nf < 8; nf++) {
            mxA = fmaxf(mxA, fmaxf(acc_s[nf][0], acc_s[nf][1]));
            mxB = fmaxf(mxB, fmaxf(acc_s[nf][2], acc_s[nf][3]));
        }
        mxA = fmaxf(mxA, __shfl_xor_sync(0xffffffffu, mxA, 1));
        mxA = fmaxf(mxA, __shfl_xor_sync(0xffffffffu, mxA, 2));
        mxB = fmaxf(mxB, __shfl_xor_sync(0xffffffffu, mxB, 1));
        mxB = fmaxf(mxB, __shfl_xor_sync(0xffffffffu, mxB, 2));
        float mnA = fmaxf(mA, mxA), mnB = fmaxf(mB, mxB);
        float scA = __expf(mA - mnA), scB = __expf(mB - mnB);
        float rsA = 0.f, rsB = 0.f;
#pragma unroll
        for (int nf = 0; nf < 8; nf++) {
            acc_s[nf][0] = __expf(acc_s[nf][0] - mnA);
            acc_s[nf][1] = __expf(acc_s[nf][1] - mnA);
            acc_s[nf][2] = __expf(acc_s[nf][2] - mnB);
            acc_s[nf][3] = __expf(acc_s[nf][3] - mnB);
            rsA += acc_s[nf][0] + acc_s[nf][1];
            rsB += acc_s[nf][2] + acc_s[nf][3];
        }
        rsA += __shfl_xor_sync(0xffffffffu, rsA, 1);
        rsA += __shfl_xor_sync(0xffffffffu, rsA, 2);
        rsB += __shfl_xor_sync(0xffffffffu, rsB, 1);
        rsB += __shfl_xor_sync(0xffffffffu, rsB, 2);
        lA = lA * scA + rsA;
        lB = lB * scB + rsB;
        mA = mnA; mB = mnB;
#pragma unroll
        for (int nf = 0; nf < 8; nf++) {
            acc_o[nf][0] *= scA; acc_o[nf][1] *= scA;
            acc_o[nf][2] *= scB; acc_o[nf][3] *= scB;
        }

        // stage P (tf32) for the PV mma
#pragma unroll
        for (int nf = 0; nf < 8; nf++) {
            int iA = (m0 + g) * FPAD + nf * 8 + 2 * tg;
            Pt[iA]     = f2tf32(acc_s[nf][0]);
            Pt[iA + 1] = f2tf32(acc_s[nf][1]);
            int iB = (m0 + g + 8) * FPAD + nf * 8 + 2 * tg;
            Pt[iB]     = f2tf32(acc_s[nf][2]);
            Pt[iB + 1] = f2tf32(acc_s[nf][3]);
        }
        __syncthreads();

        // O += P @ V  (A = P [t][s], B = V [s][d] used as col-major k x n)
#pragma unroll
        for (int ks = 0; ks < 8; ks++) {
            uint32_t a0 = Pt[(m0 + g) * FPAD + ks * 8 + tg];
            uint32_t a1 = Pt[(m0 + g + 8) * FPAD + ks * 8 + tg];
            uint32_t a2 = Pt[(m0 + g) * FPAD + ks * 8 + tg + 4];
            uint32_t a3 = Pt[(m0 + g + 8) * FPAD + ks * 8 + tg + 4];
#pragma unroll
            for (int nf = 0; nf < 8; nf++) {
                uint32_t b0 = Vs[(ks * 8 + tg) * FPAD + nf * 8 + g];
                uint32_t b1 = Vs[(ks * 8 + tg + 4) * FPAD + nf * 8 + g];
                MMA_TF32(acc_o[nf], a0, a1, a2, a3, b0, b1);
            }
        }
    }

    // normalize and write merged [T*B, E]
    float invA = 1.0f / lA, invB = 1.0f / lB;
#pragma unroll
    for (int nf = 0; nf < 8; nf++) {
        int t = t0 + m0 + g;
        int d = col + nf * 8 + 2 * tg;
        float2 v0 = { acc_o[nf][0] * invA, acc_o[nf][1] * invA };
        *(float2*)(Out + (size_t)(t * BATCH + b) * EMB + d) = v0;
        float2 v1 = { acc_o[nf][2] * invB, acc_o[nf][3] * invB };
        *(float2*)(Out + (size_t)((t + 8) * BATCH + b) * EMB + d) = v1;
    }
}

// ---------------- launch ---------------------------------------------------
extern "C" void kernel_launch(void* const* d_in, const int* in_sizes, int n_in,
                              void* d_out, int out_size)
{
    (void)in_sizes; (void)n_in; (void)out_size;
    const float* g       = (const float*)d_in[0];
    const float* h       = (const float*)d_in[1];
    const float* g_in_w  = (const float*)d_in[2];
    const float* g_in_b  = (const float*)d_in[3];
    const float* h_in_w  = (const float*)d_in[4];
    const float* h_in_b  = (const float*)d_in[5];
    const float* g_out_w = (const float*)d_in[6];
    const float* g_out_b = (const float*)d_in[7];
    const float* h_out_w = (const float*)d_in[8];
    const float* h_out_b = (const float*)d_in[9];
    float* out = (float*)d_out;

    float *qkv, *kvh, *ag, *ah;
    cudaGetSymbolAddress((void**)&qkv, sc_qkv);
    cudaGetSymbolAddress((void**)&kvh, sc_kvh);
    cudaGetSymbolAddress((void**)&ag,  sc_ag);
    cudaGetSymbolAddress((void**)&ah,  sc_ah);

    cudaFuncSetAttribute(flash_mma<0>, cudaFuncAttributeMaxDynamicSharedMemorySize,
                         FLASH_SMEM_BYTES);
    cudaFuncSetAttribute(flash_mma<1>, cudaFuncAttributeMaxDynamicSharedMemorySize,
                         FLASH_SMEM_BYTES);

    dim3 blk(256);
    // input projections on tensor cores (q scaled by 1/8: cols < 1024 of g proj)
    tf32_gemm_bias<<<dim3(3072 / 128, MROWS / 128), blk>>>(g, g_in_w, g_in_b, qkv, 3072, EMB, 1024);
    tf32_gemm_bias<<<dim3(2048 / 128, MROWS / 128), blk>>>(h, h_in_w, h_in_b, kvh, 2048, EMB, 0);
    // tensor-core fused attention
    flash_mma<0><<<dim3(T_LEN / 128, BH), blk, FLASH_SMEM_BYTES>>>(qkv, 3072, 1024, 2048, ag);
    flash_mma<1><<<dim3(T_LEN / 128, BH), blk, FLASH_SMEM_BYTES>>>(kvh, 2048, 0,    1024, ah);
    // output projections straight into d_out (g first, h second)
    tf32_gemm_bias<<<dim3(1024 / 128, MROWS / 128), blk>>>(ag, g_out_w, g_out_b, out,               1024, EMB, 0);
    tf32_gemm_bias<<<dim3(1024 / 128, MROWS / 128), blk>>>(ah, h_out_w, h_out_b, out + MROWS * EMB, 1024, EMB, 0);
}

// round 14
// speedup vs baseline: 2.6147x; 1.0672x over previous
#include <cuda_runtime.h>
#include <cstdint>
#include <math_constants.h>

#define T_LEN 1024
#define BATCH 2
#define EMB 1024
#define HEADS 16
#define HDIM 64
#define MROWS (T_LEN * BATCH)   // 2048
#define BH (BATCH * HEADS)      // 32

// ---------------- scratch (device globals; no allocation) ----------------
__device__ float sc_qkv[MROWS * 3 * EMB];   // g-stream: q | gk | gv   (2048 x 3072)
__device__ float sc_kvh[MROWS * 2 * EMB];   // h-stream: hk | hv       (2048 x 2048)
__device__ float sc_ag[MROWS * EMB];        // merged g attention out [T*B, E]
__device__ float sc_ah[MROWS * EMB];        // merged h attention out

// ---------------- threefry2x32 (JAX, key = (0, 42)) -----------------------
static __device__ __forceinline__ uint2 threefry2x32_both(uint32_t c0, uint32_t c1) {
    const uint32_t ks1 = 42u;
    const uint32_t ks2 = 0x1BD11BF0u;
    uint32_t x0 = c0;
    uint32_t x1 = c1 + ks1;
#define TF_R(r) { x0 += x1; x1 = __funnelshift_l(x1, x1, (r)); x1 ^= x0; }
    TF_R(13) TF_R(15) TF_R(26) TF_R(6)   x0 += ks1; x1 += ks2 + 1u;
    TF_R(17) TF_R(29) TF_R(16) TF_R(24)  x0 += ks2; x1 += 0u  + 2u;
    TF_R(13) TF_R(15) TF_R(26) TF_R(6)   x0 += 0u;  x1 += ks1 + 3u;
    TF_R(17) TF_R(29) TF_R(16) TF_R(24)  x0 += ks1; x1 += ks2 + 4u;
    TF_R(13) TF_R(15) TF_R(26) TF_R(6)   x0 += ks2; x1 += 0u  + 5u;
#undef TF_R
    return make_uint2(x0, x1);
}

// JAX partitionable mode: counts (0, i); output = w0 ^ w1. (VERIFIED R10)
static __device__ __forceinline__ uint32_t jax_bits(uint32_t idx) {
    uint2 w = threefry2x32_both(0u, idx);
    return w.x ^ w.y;
}

// gumbel noise; inner log via MUFU (__logf) — error ~2^-22 abs, invisible
static __device__ __forceinline__ float gumbel_noise(uint32_t idx) {
    uint32_t y = jax_bits(idx);
    float u = __uint_as_float((y >> 9) | 0x3f800000u) - 1.0f;
    float inner = -__logf(u + 1e-20f) + 1e-20f;
    return -__logf(inner);
}

// ---------------- tf32 helpers ---------------------------------------------
static __device__ __forceinline__ uint32_t f2tf32(float f) {
    uint32_t r;
    asm("cvt.rna.tf32.f32 %0, %1;" : "=r"(r) : "f"(f));
    return r;
}

#define MMA_TF32(acc, a0, a1, a2, a3, b0, b1)                                  \
    asm volatile(                                                              \
        "mma.sync.aligned.m16n8k8.row.col.f32.tf32.tf32.f32 "                  \
        "{%0,%1,%2,%3}, {%4,%5,%6,%7}, {%8,%9}, {%0,%1,%2,%3};"                \
        : "+f"((acc)[0]), "+f"((acc)[1]), "+f"((acc)[2]), "+f"((acc)[3])       \
        : "r"(a0), "r"(a1), "r"(a2), "r"(a3), "r"(b0), "r"(b1))

// ---------------- tf32 tensor-core GEMM: C = A[M,K] @ W[N,K]^T + bias ------
// (verified R12) 128x128 block tile, BK=32, 8 warps, m16n8k8 tf32.
__global__ __launch_bounds__(256) void tf32_gemm_bias(
    const float* __restrict__ A, const float* __restrict__ W,
    const float* __restrict__ bias, float* __restrict__ C,
    int N, int K, int scale_cols)
{
    __shared__ uint32_t As[128 * 36];
    __shared__ uint32_t Bs[128 * 36];
    const int bm = blockIdx.y * 128;
    const int bn = blockIdx.x * 128;
    const int tid = threadIdx.x;
    const int lane = tid & 31, warp = tid >> 5;
    const int warpM = warp & 1, warpN = warp >> 1;
    const int mbase = warpM * 64, nbase = warpN * 32;
    const int g = lane >> 2, tg = lane & 3;

    float acc[4][4][4];
#pragma unroll
    for (int mt = 0; mt < 4; mt++)
#pragma unroll
        for (int nt = 0; nt < 4; nt++)
#pragma unroll
            for (int c = 0; c < 4; c++) acc[mt][nt][c] = 0.f;

    const float* Ab = A + (size_t)bm * K;
    const float* Wb = W + (size_t)bn * K;

    float4 stA[4], stB[4];
#pragma unroll
    for (int i = 0; i < 4; i++) {
        int idx = i * 256 + tid;
        int row = idx >> 3, c4 = (idx & 7) << 2;
        stA[i] = *(const float4*)(Ab + (size_t)row * K + c4);
        stB[i] = *(const float4*)(Wb + (size_t)row * K + c4);
    }
#pragma unroll
    for (int i = 0; i < 4; i++) {
        int idx = i * 256 + tid;
        int row = idx >> 3, c4 = (idx & 7) << 2;
        uint4 a4 = { f2tf32(stA[i].x), f2tf32(stA[i].y), f2tf32(stA[i].z), f2tf32(stA[i].w) };
        *(uint4*)&As[row * 36 + c4] = a4;
        uint4 b4 = { f2tf32(stB[i].x), f2tf32(stB[i].y), f2tf32(stB[i].z), f2tf32(stB[i].w) };
        *(uint4*)&Bs[row * 36 + c4] = b4;
    }
    __syncthreads();

    for (int k0 = 0; k0 < K; k0 += 32) {
        const bool has_next = (k0 + 32) < K;
        if (has_next) {
#pragma unroll
            for (int i = 0; i < 4; i++) {
                int idx = i * 256 + tid;
                int row = idx >> 3, c4 = (idx & 7) << 2;
                stA[i] = *(const float4*)(Ab + (size_t)row * K + k0 + 32 + c4);
                stB[i] = *(const float4*)(Wb + (size_t)row * K + k0 + 32 + c4);
            }
        }
#pragma unroll
        for (int ks = 0; ks < 32; ks += 8) {
            uint32_t af[4][4], bf[4][2];
#pragma unroll
            for (int mt = 0; mt < 4; mt++) {
                int r0 = (mbase + mt * 16 + g) * 36 + ks + tg;
                af[mt][0] = As[r0];
                af[mt][1] = As[r0 + 8 * 36];
                af[mt][2] = As[r0 + 4];
                af[mt][3] = As[r0 + 8 * 36 + 4];
            }
#pragma unroll
            for (int nt = 0; nt < 4; nt++) {
                int r0 = (nbase + nt * 8 + g) * 36 + ks + tg;
                bf[nt][0] = Bs[r0];
                bf[nt][1] = Bs[r0 + 4];
            }
#pragma unroll
            for (int mt = 0; mt < 4; mt++)
#pragma unroll
                for (int nt = 0; nt < 4; nt++)
                    MMA_TF32(acc[mt][nt], af[mt][0], af[mt][1], af[mt][2], af[mt][3],
                             bf[nt][0], bf[nt][1]);
        }
        if (has_next) {
            __syncthreads();
#pragma unroll
            for (int i = 0; i < 4; i++) {
                int idx = i * 256 + tid;
                int row = idx >> 3, c4 = (idx & 7) << 2;
                uint4 a4 = { f2tf32(stA[i].x), f2tf32(stA[i].y), f2tf32(stA[i].z), f2tf32(stA[i].w) };
                *(uint4*)&As[row * 36 + c4] = a4;
                uint4 b4 = { f2tf32(stB[i].x), f2tf32(stB[i].y), f2tf32(stB[i].z), f2tf32(stB[i].w) };
                *(uint4*)&Bs[row * 36 + c4] = b4;
            }
            __syncthreads();
        }
    }

#pragma unroll
    for (int mt = 0; mt < 4; mt++) {
        int row = bm + mbase + mt * 16 + g;
#pragma unroll
        for (int nt = 0; nt < 4; nt++) {
            int c0 = bn + nbase + nt * 8 + 2 * tg;
            float bx = bias[c0], by = bias[c0 + 1];
            float2 v0 = { acc[mt][nt][0] + bx, acc[mt][nt][1] + by };
            float2 v1 = { acc[mt][nt][2] + bx, acc[mt][nt][3] + by };
            if (c0 < scale_cols) {
                v0.x *= 0.125f; v0.y *= 0.125f; v1.x *= 0.125f; v1.y *= 0.125f;
            }
            *(float2*)(C + (size_t)row * N + c0) = v0;
            *(float2*)(C + (size_t)(row + 8) * N + c0) = v1;
        }
    }
}

// ---------------- tensor-core fused flash attention ------------------------
// BM=128 t-rows/block, 64 s-cols per iteration, 8 warps each m16 x n64.
// Gumbel noise computed phase-isolated into the Pt smem buffer (low regs),
// then added to score fragments; P overwrites the same slots (same-thread).
#define FPAD 68
#define SM_Q  0                       // [128][68]
#define SM_K  (128 * FPAD)            // [64][68]
#define SM_V  (128 * FPAD + 64 * FPAD)
#define SM_P  (128 * FPAD + 2 * 64 * FPAD)
#define FLASH_SMEM_BYTES ((2 * 128 * FPAD + 2 * 64 * FPAD) * 4)

template<int DO_GUMBEL>
__global__ __launch_bounds__(256, 2) void flash_mma(
    const float* __restrict__ KVsrc, int ldkv, int koff, int voff,
    float* __restrict__ Out)
{
    extern __shared__ uint32_t sm[];
    uint32_t* Qs = sm + SM_Q;
    uint32_t* Ks = sm + SM_K;
    uint32_t* Vs = sm + SM_V;
    uint32_t* Pt = sm + SM_P;

    const int t0 = blockIdx.x * 128;
    const int bh = blockIdx.y;
    const int b = bh >> 4, hh = bh & 15;
    const int col = hh * HDIM;
    const int tid = threadIdx.x;
    const int lane = tid & 31, warp = tid >> 5;
    const int g = lane >> 2, tg = lane & 3;
    const int m0 = warp * 16;

    // load Q tile [128 t][64 j] as tf32
#pragma unroll
    for (int r = 0; r < 8; r++) {
        int fi = r * 256 + tid;
        int row = fi >> 4, jq = (fi & 15) << 2;
        float4 q = *(const float4*)(sc_qkv + (size_t)((t0 + row) * BATCH + b) * 3072 + col + jq);
        uint4 u = { f2tf32(q.x), f2tf32(q.y), f2tf32(q.z), f2tf32(q.w) };
        *(uint4*)&Qs[row * FPAD + jq] = u;
    }

    float acc_o[8][4];
#pragma unroll
    for (int nf = 0; nf < 8; nf++)
#pragma unroll
        for (int c = 0; c < 4; c++) acc_o[nf][c] = 0.f;
    float mA = -CUDART_INF_F, mB = -CUDART_INF_F, lA = 0.f, lB = 0.f;

    for (int sk = 0; sk < T_LEN; sk += 64) {
        __syncthreads();   // previous PV readers of Ks/Vs/Pt done
#pragma unroll
        for (int r = 0; r < 4; r++) {
            int fi = r * 256 + tid;
            int row = fi >> 4, jq = (fi & 15) << 2;
            const float* src = KVsrc + (size_t)((sk + row) * BATCH + b) * ldkv;
            float4 kk = *(const float4*)(src + koff + col + jq);
            uint4 uk = { f2tf32(kk.x), f2tf32(kk.y), f2tf32(kk.z), f2tf32(kk.w) };
            *(uint4*)&Ks[row * FPAD + jq] = uk;
            float4 vv = *(const float4*)(src + voff + col + jq);
            uint4 uv = { f2tf32(vv.x), f2tf32(vv.y), f2tf32(vv.z), f2tf32(vv.w) };
            *(uint4*)&Vs[row * FPAD + jq] = uv;
        }

        if (DO_GUMBEL) {
            // phase-isolated RNG: 8192 noise values -> Pt[t][s]; 32 per thread
            int r = tid >> 1;
            int cb = (tid & 1) * 32;
            uint32_t ibase = ((uint32_t)bh << 20) + ((uint32_t)(t0 + r) << 10)
                           + (uint32_t)(sk + cb);
            uint32_t* dst = &Pt[r * FPAD + cb];
#pragma unroll
            for (int c = 0; c < 32; c += 8) {
                float n[8];
#pragma unroll
                for (int j = 0; j < 8; j++) n[j] = gumbel_noise(ibase + c + j);
#pragma unroll
                for (int j = 0; j < 8; j++) dst[c + j] = __float_as_uint(n[j]);
            }
        }
        __syncthreads();

        // S = Q @ K^T : warp rows [m0, m0+16), all 64 cols
        float acc_s[8][4];
#pragma unroll
        for (int nf = 0; nf < 8; nf++)
#pragma unroll
            for (int c = 0; c < 4; c++) acc_s[nf][c] = 0.f;
#pragma unroll
        for (int ks = 0; ks < 8; ks++) {
            uint32_t a0 = Qs[(m0 + g) * FPAD + ks * 8 + tg];
            uint32_t a1 = Qs[(m0 + g + 8) * FPAD + ks * 8 + tg];
            uint32_t a2 = Qs[(m0 + g) * FPAD + ks * 8 + tg + 4];
            uint32_t a3 = Qs[(m0 + g + 8) * FPAD + ks * 8 + tg + 4];
#pragma unroll
            for (int nf = 0; nf < 8; nf++) {
                uint32_t b0 = Ks[(nf * 8 + g) * FPAD + ks * 8 + tg];
                uint32_t b1 = Ks[(nf * 8 + g) * FPAD + ks * 8 + tg + 4];
                MMA_TF32(acc_s[nf], a0, a1, a2, a3, b0, b1);
            }
        }

        if (DO_GUMBEL) {
            // add noise from Pt; slot (t,s) owner == this thread (also P writer)
#pragma unroll
            for (int nf = 0; nf < 8; nf++) {
                int iA = (m0 + g) * FPAD + nf * 8 + 2 * tg;
                acc_s[nf][0] += __uint_as_float(Pt[iA]);
                acc_s[nf][1] += __uint_as_float(Pt[iA + 1]);
                int iB = (m0 + g + 8) * FPAD + nf * 8 + 2 * tg;
                acc_s[nf][2] += __uint_as_float(Pt[iB]);
                acc_s[nf][3] += __uint_as_float(Pt[iB + 1]);
            }
        }

        // online softmax: rows (m0+g) [c0,c1] and (m0+g+8) [c2,c3],
        // full row lives in the 4-lane tg quad -> 2 shfls.
        float mxA = -CUDART_INF_F, mxB = -CUDART_INF_F;
#pragma unroll
        for (int nf = 0; nf < 8; nf++) {
            mxA = fmaxf(mxA, fmaxf(acc_s[nf][0], acc_s[nf][1]));
            mxB = fmaxf(mxB, fmaxf(acc_s[nf][2], acc_s[nf][3]));
        }
        mxA = fmaxf(mxA, __shfl_xor_sync(0xffffffffu, mxA, 1));
        mxA = fmaxf(mxA, __shfl_xor_sync(0xffffffffu, mxA, 2));
        mxB = fmaxf(mxB, __shfl_xor_sync(0xffffffffu, mxB, 1));
        mxB = fmaxf(mxB, __shfl_xor_sync(0xffffffffu, mxB, 2));
        float mnA = fmaxf(mA, mxA), mnB = fmaxf(mB, mxB);
        float scA = __expf(mA - mnA), scB = __expf(mB - mnB);
        float rsA = 0.f, rsB = 0.f;
#pragma unroll
        for (int nf = 0; nf < 8; nf++) {
            acc_s[nf][0] = __expf(acc_s[nf][0] - mnA);
            acc_s[nf][1] = __expf(acc_s[nf][1] - mnA);
            acc_s[nf][2] = __expf(acc_s[nf][2] - mnB);
            acc_s[nf][3] = __expf(acc_s[nf][3] - mnB);
            rsA += acc_s[nf][0] + acc_s[nf][1];
            rsB += acc_s[nf][2] + acc_s[nf][3];
        }
        rsA += __shfl_xor_sync(0xffffffffu, rsA, 1);
        rsA += __shfl_xor_sync(0xffffffffu, rsA, 2);
        rsB += __shfl_xor_sync(0xffffffffu, rsB, 1);
        rsB += __shfl_xor_sync(0xffffffffu, rsB, 2);
        lA = lA * scA + rsA;
        lB = lB * scB + rsB;
        mA = mnA; mB = mnB;
#pragma unroll
        for (int nf = 0; nf < 8; nf++) {
            acc_o[nf][0] *= scA; acc_o[nf][1] *= scA;
            acc_o[nf][2] *= scB; acc_o[nf][3] *= scB;
        }

        // stage P (tf32) for the PV mma (same slots this thread read noise from)
#pragma unroll
        for (int nf = 0; nf < 8; nf++) {
            int iA = (m0 + g) * FPAD + nf * 8 + 2 * tg;
            Pt[iA]     = f2tf32(acc_s[nf][0]);
            Pt[iA + 1] = f2tf32(acc_s[nf][1]);
            int iB = (m0 + g + 8) * FPAD + nf * 8 + 2 * tg;
            Pt[iB]     = f2tf32(acc_s[nf][2]);
            Pt[iB + 1] = f2tf32(acc_s[nf][3]);
        }
        __syncthreads();

        // O += P @ V  (A = P [t][s], B = V [s][d] used as col-major k x n)
#pragma unroll
        for (int ks = 0; ks < 8; ks++) {
            uint32_t a0 = Pt[(m0 + g) * FPAD + ks * 8 + tg];
            uint32_t a1 = Pt[(m0 + g + 8) * FPAD + ks * 8 + tg];
            uint32_t a2 = Pt[(m0 + g) * FPAD + ks * 8 + tg + 4];
            uint32_t a3 = Pt[(m0 + g + 8) * FPAD + ks * 8 + tg + 4];
#pragma unroll
            for (int nf = 0; nf < 8; nf++) {
                uint32_t b0 = Vs[(ks * 8 + tg) * FPAD + nf * 8 + g];
                uint32_t b1 = Vs[(ks * 8 + tg + 4) * FPAD + nf * 8 + g];
                MMA_TF32(acc_o[nf], a0, a1, a2, a3, b0, b1);
            }
        }
    }

    // normalize and write merged [T*B, E]
    float invA = 1.0f / lA, invB = 1.0f / lB;
#pragma unroll
    for (int nf = 0; nf < 8; nf++) {
        int t = t0 + m0 + g;
        int d = col + nf * 8 + 2 * tg;
        float2 v0 = { acc_o[nf][0] * invA, acc_o[nf][1] * invA };
        *(float2*)(Out + (size_t)(t * BATCH + b) * EMB + d) = v0;
        float2 v1 = { acc_o[nf][2] * invB, acc_o[nf][3] * invB };
        *(float2*)(Out + (size_t)((t + 8) * BATCH + b) * EMB + d) = v1;
    }
}

// ---------------- launch ---------------------------------------------------
extern "C" void kernel_launch(void* const* d_in, const int* in_sizes, int n_in,
                              void* d_out, int out_size)
{
    (void)in_sizes; (void)n_in; (void)out_size;
    const float* g       = (const float*)d_in[0];
    const float* h       = (const float*)d_in[1];
    const float* g_in_w  = (const float*)d_in[2];
    const float* g_in_b  = (const float*)d_in[3];
    const float* h_in_w  = (const float*)d_in[4];
    const float* h_in_b  = (const float*)d_in[5];
    const float* g_out_w = (const float*)d_in[6];
    const float* g_out_b = (const float*)d_in[7];
    const float* h_out_w = (const float*)d_in[8];
    const float* h_out_b = (const float*)d_in[9];
    float* out = (float*)d_out;

    float *qkv, *kvh, *ag, *ah;
    cudaGetSymbolAddress((void**)&qkv, sc_qkv);
    cudaGetSymbolAddress((void**)&kvh, sc_kvh);
    cudaGetSymbolAddress((void**)&ag,  sc_ag);
    cudaGetSymbolAddress((void**)&ah,  sc_ah);

    cudaFuncSetAttribute(flash_mma<0>, cudaFuncAttributeMaxDynamicSharedMemorySize,
                         FLASH_SMEM_BYTES);
    cudaFuncSetAttribute(flash_mma<1>, cudaFuncAttributeMaxDynamicSharedMemorySize,
                         FLASH_SMEM_BYTES);

    dim3 blk(256);
    // input projections on tensor cores (q scaled by 1/8: cols < 1024 of g proj)
    tf32_gemm_bias<<<dim3(3072 / 128, MROWS / 128), blk>>>(g, g_in_w, g_in_b, qkv, 3072, EMB, 1024);
    tf32_gemm_bias<<<dim3(2048 / 128, MROWS / 128), blk>>>(h, h_in_w, h_in_b, kvh, 2048, EMB, 0);
    // tensor-core fused attention
    flash_mma<0><<<dim3(T_LEN / 128, BH), blk, FLASH_SMEM_BYTES>>>(qkv, 3072, 1024, 2048, ag);
    flash_mma<1><<<dim3(T_LEN / 128, BH), blk, FLASH_SMEM_BYTES>>>(kvh, 2048, 0,    1024, ah);
    // output projections straight into d_out (g first, h second)
    tf32_gemm_bias<<<dim3(1024 / 128, MROWS / 128), blk>>>(ag, g_out_w, g_out_b, out,               1024, EMB, 0);
    tf32_gemm_bias<<<dim3(1024 / 128, MROWS / 128), blk>>>(ah, h_out_w, h_out_b, out + MROWS * EMB, 1024, EMB, 0);
}

// round 15
// speedup vs baseline: 2.6800x; 1.0250x over previous
#include <cuda_runtime.h>
#include <cstdint>
#include <math_constants.h>

#define T_LEN 1024
#define BATCH 2
#define EMB 1024
#define HEADS 16
#define HDIM 64
#define MROWS (T_LEN * BATCH)   // 2048
#define BH (BATCH * HEADS)      // 32

// ---------------- scratch (device globals; no allocation) ----------------
__device__ float sc_qkv[MROWS * 3 * EMB];   // g-stream: q | gk | gv   (2048 x 3072)
__device__ float sc_kvh[MROWS * 2 * EMB];   // h-stream: hk | hv       (2048 x 2048)
__device__ float sc_ag[MROWS * EMB];        // merged g attention out [T*B, E]
__device__ float sc_ah[MROWS * EMB];        // merged h attention out

// ---------------- threefry2x32 (JAX, key = (0, 42)) -----------------------
static __device__ __forceinline__ uint2 threefry2x32_both(uint32_t c0, uint32_t c1) {
    const uint32_t ks1 = 42u;
    const uint32_t ks2 = 0x1BD11BF0u;
    uint32_t x0 = c0;
    uint32_t x1 = c1 + ks1;
#define TF_R(r) { x0 += x1; x1 = __funnelshift_l(x1, x1, (r)); x1 ^= x0; }
    TF_R(13) TF_R(15) TF_R(26) TF_R(6)   x0 += ks1; x1 += ks2 + 1u;
    TF_R(17) TF_R(29) TF_R(16) TF_R(24)  x0 += ks2; x1 += 0u  + 2u;
    TF_R(13) TF_R(15) TF_R(26) TF_R(6)   x0 += 0u;  x1 += ks1 + 3u;
    TF_R(17) TF_R(29) TF_R(16) TF_R(24)  x0 += ks1; x1 += ks2 + 4u;
    TF_R(13) TF_R(15) TF_R(26) TF_R(6)   x0 += ks2; x1 += 0u  + 5u;
#undef TF_R
    return make_uint2(x0, x1);
}

// JAX partitionable mode: counts (0, i); output = w0 ^ w1. (VERIFIED R10)
static __device__ __forceinline__ uint32_t jax_bits(uint32_t idx) {
    uint2 w = threefry2x32_both(0u, idx);
    return w.x ^ w.y;
}

// gumbel noise; inner log via MUFU (__logf) — error ~2^-22 abs, invisible
static __device__ __forceinline__ float gumbel_noise(uint32_t idx) {
    uint32_t y = jax_bits(idx);
    float u = __uint_as_float((y >> 9) | 0x3f800000u) - 1.0f;
    float inner = -__logf(u + 1e-20f) + 1e-20f;
    return -__logf(inner);
}

// ---------------- tf32 helpers ---------------------------------------------
static __device__ __forceinline__ uint32_t f2tf32(float f) {
    uint32_t r;
    asm("cvt.rna.tf32.f32 %0, %1;" : "=r"(r) : "f"(f));
    return r;
}

#define MMA_TF32(acc, a0, a1, a2, a3, b0, b1)                                  \
    asm volatile(                                                              \
        "mma.sync.aligned.m16n8k8.row.col.f32.tf32.tf32.f32 "                  \
        "{%0,%1,%2,%3}, {%4,%5,%6,%7}, {%8,%9}, {%0,%1,%2,%3};"                \
        : "+f"((acc)[0]), "+f"((acc)[1]), "+f"((acc)[2]), "+f"((acc)[3])       \
        : "r"(a0), "r"(a1), "r"(a2), "r"(a3), "r"(b0), "r"(b1))

// ---------------- dual tf32 GEMM: two independent C = A@W^T + bias ---------
// Block-routed batching: blocks with blockIdx.x < split do GEMM 0, the rest
// GEMM 1. Both have M = 2048 (blockIdx.y) and K = 1024. (math verified R12)
__global__ __launch_bounds__(256) void tf32_gemm_dual(
    const float* __restrict__ A0, const float* __restrict__ W0,
    const float* __restrict__ b0, float* __restrict__ C0, int N0, int sc0, int split,
    const float* __restrict__ A1, const float* __restrict__ W1,
    const float* __restrict__ b1, float* __restrict__ C1, int N1, int sc1)
{
    const int K = 1024;
    __shared__ uint32_t As[128 * 36];
    __shared__ uint32_t Bs[128 * 36];

    const float* A; const float* W; const float* bias; float* C;
    int N, scale_cols, bnx;
    if (blockIdx.x < (unsigned)split) {
        A = A0; W = W0; bias = b0; C = C0; N = N0; scale_cols = sc0; bnx = blockIdx.x;
    } else {
        A = A1; W = W1; bias = b1; C = C1; N = N1; scale_cols = sc1; bnx = blockIdx.x - split;
    }
    const int bm = blockIdx.y * 128;
    const int bn = bnx * 128;
    const int tid = threadIdx.x;
    const int lane = tid & 31, warp = tid >> 5;
    const int warpM = warp & 1, warpN = warp >> 1;
    const int mbase = warpM * 64, nbase = warpN * 32;
    const int g = lane >> 2, tg = lane & 3;

    float acc[4][4][4];
#pragma unroll
    for (int mt = 0; mt < 4; mt++)
#pragma unroll
        for (int nt = 0; nt < 4; nt++)
#pragma unroll
            for (int c = 0; c < 4; c++) acc[mt][nt][c] = 0.f;

    const float* Ab = A + (size_t)bm * K;
    const float* Wb = W + (size_t)bn * K;

    float4 stA[4], stB[4];
#pragma unroll
    for (int i = 0; i < 4; i++) {
        int idx = i * 256 + tid;
        int row = idx >> 3, c4 = (idx & 7) << 2;
        stA[i] = *(const float4*)(Ab + (size_t)row * K + c4);
        stB[i] = *(const float4*)(Wb + (size_t)row * K + c4);
    }
#pragma unroll
    for (int i = 0; i < 4; i++) {
        int idx = i * 256 + tid;
        int row = idx >> 3, c4 = (idx & 7) << 2;
        uint4 a4 = { f2tf32(stA[i].x), f2tf32(stA[i].y), f2tf32(stA[i].z), f2tf32(stA[i].w) };
        *(uint4*)&As[row * 36 + c4] = a4;
        uint4 b4 = { f2tf32(stB[i].x), f2tf32(stB[i].y), f2tf32(stB[i].z), f2tf32(stB[i].w) };
        *(uint4*)&Bs[row * 36 + c4] = b4;
    }
    __syncthreads();

    for (int k0 = 0; k0 < K; k0 += 32) {
        const bool has_next = (k0 + 32) < K;
        if (has_next) {
#pragma unroll
            for (int i = 0; i < 4; i++) {
                int idx = i * 256 + tid;
                int row = idx >> 3, c4 = (idx & 7) << 2;
                stA[i] = *(const float4*)(Ab + (size_t)row * K + k0 + 32 + c4);
                stB[i] = *(const float4*)(Wb + (size_t)row * K + k0 + 32 + c4);
            }
        }
#pragma unroll
        for (int ks = 0; ks < 32; ks += 8) {
            uint32_t af[4][4], bf[4][2];
#pragma unroll
            for (int mt = 0; mt < 4; mt++) {
                int r0 = (mbase + mt * 16 + g) * 36 + ks + tg;
                af[mt][0] = As[r0];
                af[mt][1] = As[r0 + 8 * 36];
                af[mt][2] = As[r0 + 4];
                af[mt][3] = As[r0 + 8 * 36 + 4];
            }
#pragma unroll
            for (int nt = 0; nt < 4; nt++) {
                int r0 = (nbase + nt * 8 + g) * 36 + ks + tg;
                bf[nt][0] = Bs[r0];
                bf[nt][1] = Bs[r0 + 4];
            }
#pragma unroll
            for (int mt = 0; mt < 4; mt++)
#pragma unroll
                for (int nt = 0; nt < 4; nt++)
                    MMA_TF32(acc[mt][nt], af[mt][0], af[mt][1], af[mt][2], af[mt][3],
                             bf[nt][0], bf[nt][1]);
        }
        if (has_next) {
            __syncthreads();
#pragma unroll
            for (int i = 0; i < 4; i++) {
                int idx = i * 256 + tid;
                int row = idx >> 3, c4 = (idx & 7) << 2;
                uint4 a4 = { f2tf32(stA[i].x), f2tf32(stA[i].y), f2tf32(stA[i].z), f2tf32(stA[i].w) };
                *(uint4*)&As[row * 36 + c4] = a4;
                uint4 b4 = { f2tf32(stB[i].x), f2tf32(stB[i].y), f2tf32(stB[i].z), f2tf32(stB[i].w) };
                *(uint4*)&Bs[row * 36 + c4] = b4;
            }
            __syncthreads();
        }
    }

#pragma unroll
    for (int mt = 0; mt < 4; mt++) {
        int row = bm + mbase + mt * 16 + g;
#pragma unroll
        for (int nt = 0; nt < 4; nt++) {
            int c0 = bn + nbase + nt * 8 + 2 * tg;
            float bx = bias[c0], by = bias[c0 + 1];
            float2 v0 = { acc[mt][nt][0] + bx, acc[mt][nt][1] + by };
            float2 v1 = { acc[mt][nt][2] + bx, acc[mt][nt][3] + by };
            if (c0 < scale_cols) {
                v0.x *= 0.125f; v0.y *= 0.125f; v1.x *= 0.125f; v1.y *= 0.125f;
            }
            *(float2*)(C + (size_t)row * N + c0) = v0;
            *(float2*)(C + (size_t)(row + 8) * N + c0) = v1;
        }
    }
}

// ---------------- dual tensor-core fused flash attention -------------------
// Both attention streams in ONE launch: blockIdx.x & 1 selects stream
// (0 = g: plain softmax; 1 = h: gumbel softmax). Interleaved so alternating
// blocks co-resident on an SM mix ALU-heavy (RNG) and tensor-heavy phases.
#define FPAD 68
#define SM_Q  0                       // [128][68]
#define SM_K  (128 * FPAD)            // [64][68]
#define SM_V  (128 * FPAD + 64 * FPAD)
#define SM_P  (128 * FPAD + 2 * 64 * FPAD)
#define FLASH_SMEM_BYTES ((2 * 128 * FPAD + 2 * 64 * FPAD) * 4)

__global__ __launch_bounds__(256, 2) void flash_mma_dual()
{
    extern __shared__ uint32_t sm[];
    uint32_t* Qs = sm + SM_Q;
    uint32_t* Ks = sm + SM_K;
    uint32_t* Vs = sm + SM_V;
    uint32_t* Pt = sm + SM_P;

    const int stream = blockIdx.x & 1;          // 0 = g, 1 = h
    const int t0 = (blockIdx.x >> 1) * 128;
    const int bh = blockIdx.y;
    const int b = bh >> 4, hh = bh & 15;
    const int col = hh * HDIM;
    const int tid = threadIdx.x;
    const int lane = tid & 31, warp = tid >> 5;
    const int g = lane >> 2, tg = lane & 3;
    const int m0 = warp * 16;

    const float* KVsrc = stream ? sc_kvh : sc_qkv;
    const int ldkv = stream ? 2048 : 3072;
    const int koff = stream ? 0 : 1024;
    const int voff = stream ? 1024 : 2048;
    float* Out = stream ? sc_ah : sc_ag;
    const bool do_gumbel = (stream == 1);

    // load Q tile [128 t][64 j] as tf32 (Q always from sc_qkv)
#pragma unroll
    for (int r = 0; r < 8; r++) {
        int fi = r * 256 + tid;
        int row = fi >> 4, jq = (fi & 15) << 2;
        float4 q = *(const float4*)(sc_qkv + (size_t)((t0 + row) * BATCH + b) * 3072 + col + jq);
        uint4 u = { f2tf32(q.x), f2tf32(q.y), f2tf32(q.z), f2tf32(q.w) };
        *(uint4*)&Qs[row * FPAD + jq] = u;
    }

    float acc_o[8][4];
#pragma unroll
    for (int nf = 0; nf < 8; nf++)
#pragma unroll
        for (int c = 0; c < 4; c++) acc_o[nf][c] = 0.f;
    float mA = -CUDART_INF_F, mB = -CUDART_INF_F, lA = 0.f, lB = 0.f;

    for (int sk = 0; sk < T_LEN; sk += 64) {
        __syncthreads();   // previous PV readers of Ks/Vs/Pt done
#pragma unroll
        for (int r = 0; r < 4; r++) {
            int fi = r * 256 + tid;
            int row = fi >> 4, jq = (fi & 15) << 2;
            const float* src = KVsrc + (size_t)((sk + row) * BATCH + b) * ldkv;
            float4 kk = *(const float4*)(src + koff + col + jq);
            uint4 uk = { f2tf32(kk.x), f2tf32(kk.y), f2tf32(kk.z), f2tf32(kk.w) };
            *(uint4*)&Ks[row * FPAD + jq] = uk;
            float4 vv = *(const float4*)(src + voff + col + jq);
            uint4 uv = { f2tf32(vv.x), f2tf32(vv.y), f2tf32(vv.z), f2tf32(vv.w) };
            *(uint4*)&Vs[row * FPAD + jq] = uv;
        }

        if (do_gumbel) {
            // phase-isolated RNG: 8192 noise values -> Pt[t][s]; 32 per thread
            int r = tid >> 1;
            int cb = (tid & 1) * 32;
            uint32_t ibase = ((uint32_t)bh << 20) + ((uint32_t)(t0 + r) << 10)
                           + (uint32_t)(sk + cb);
            uint32_t* dst = &Pt[r * FPAD + cb];
#pragma unroll
            for (int c = 0; c < 32; c += 8) {
                float n[8];
#pragma unroll
                for (int j = 0; j < 8; j++) n[j] = gumbel_noise(ibase + c + j);
#pragma unroll
                for (int j = 0; j < 8; j++) dst[c + j] = __float_as_uint(n[j]);
            }
        }
        __syncthreads();

        // S = Q @ K^T : warp rows [m0, m0+16), all 64 cols
        float acc_s[8][4];
#pragma unroll
        for (int nf = 0; nf < 8; nf++)
#pragma unroll
            for (int c = 0; c < 4; c++) acc_s[nf][c] = 0.f;
#pragma unroll
        for (int ks = 0; ks < 8; ks++) {
            uint32_t a0 = Qs[(m0 + g) * FPAD + ks * 8 + tg];
            uint32_t a1 = Qs[(m0 + g + 8) * FPAD + ks * 8 + tg];
            uint32_t a2 = Qs[(m0 + g) * FPAD + ks * 8 + tg + 4];
            uint32_t a3 = Qs[(m0 + g + 8) * FPAD + ks * 8 + tg + 4];
#pragma unroll
            for (int nf = 0; nf < 8; nf++) {
                uint32_t b0 = Ks[(nf * 8 + g) * FPAD + ks * 8 + tg];
                uint32_t b1 = Ks[(nf * 8 + g) * FPAD + ks * 8 + tg + 4];
                MMA_TF32(acc_s[nf], a0, a1, a2, a3, b0, b1);
            }
        }

        if (do_gumbel) {
            // add noise from Pt; slot (t,s) owner == this thread (also P writer)
#pragma unroll
            for (int nf = 0; nf < 8; nf++) {
                int iA = (m0 + g) * FPAD + nf * 8 + 2 * tg;
                acc_s[nf][0] += __uint_as_float(Pt[iA]);
                acc_s[nf][1] += __uint_as_float(Pt[iA + 1]);
                int iB = (m0 + g + 8) * FPAD + nf * 8 + 2 * tg;
                acc_s[nf][2] += __uint_as_float(Pt[iB]);
                acc_s[nf][3] += __uint_as_float(Pt[iB + 1]);
            }
        }

        // online softmax: rows (m0+g) [c0,c1] and (m0+g+8) [c2,c3],
        // full row lives in the 4-lane tg quad -> 2 shfls.
        float mxA = -CUDART_INF_F, mxB = -CUDART_INF_F;
#pragma unroll
        for (int nf = 0; nf < 8; nf++) {
            mxA = fmaxf(mxA, fmaxf(acc_s[nf][0], acc_s[nf][1]));
            mxB = fmaxf(mxB, fmaxf(acc_s[nf][2], acc_s[nf][3]));
        }
        mxA = fmaxf(mxA, __shfl_xor_sync(0xffffffffu, mxA, 1));
        mxA = fmaxf(mxA, __shfl_xor_sync(0xffffffffu, mxA, 2));
        mxB = fmaxf(mxB, __shfl_xor_sync(0xffffffffu, mxB, 1));
        mxB = fmaxf(mxB, __shfl_xor_sync(0xffffffffu, mxB, 2));
        float mnA = fmaxf(mA, mxA), mnB = fmaxf(mB, mxB);
        float scA = __expf(mA - mnA), scB = __expf(mB - mnB);
        float rsA = 0.f, rsB = 0.f;
#pragma unroll
        for (int nf = 0; nf < 8; nf++) {
            acc_s[nf][0] = __expf(acc_s[nf][0] - mnA);
            acc_s[nf][1] = __expf(acc_s[nf][1] - mnA);
            acc_s[nf][2] = __expf(acc_s[nf][2] - mnB);
            acc_s[nf][3] = __expf(acc_s[nf][3] - mnB);
            rsA += acc_s[nf][0] + acc_s[nf][1];
            rsB += acc_s[nf][2] + acc_s[nf][3];
        }
        rsA += __shfl_xor_sync(0xffffffffu, rsA, 1);
        rsA += __shfl_xor_sync(0xffffffffu, rsA, 2);
        rsB += __shfl_xor_sync(0xffffffffu, rsB, 1);
        rsB += __shfl_xor_sync(0xffffffffu, rsB, 2);
        lA = lA * scA + rsA;
        lB = lB * scB + rsB;
        mA = mnA; mB = mnB;
#pragma unroll
        for (int nf = 0; nf < 8; nf++) {
            acc_o[nf][0] *= scA; acc_o[nf][1] *= scA;
            acc_o[nf][2] *= scB; acc_o[nf][3] *= scB;
        }

        // stage P (tf32) for the PV mma (same slots this thread read noise from)
#pragma unroll
        for (int nf = 0; nf < 8; nf++) {
            int iA = (m0 + g) * FPAD + nf * 8 + 2 * tg;
            Pt[iA]     = f2tf32(acc_s[nf][0]);
            Pt[iA + 1] = f2tf32(acc_s[nf][1]);
            int iB = (m0 + g + 8) * FPAD + nf * 8 + 2 * tg;
            Pt[iB]     = f2tf32(acc_s[nf][2]);
            Pt[iB + 1] = f2tf32(acc_s[nf][3]);
        }
        __syncthreads();

        // O += P @ V  (A = P [t][s], B = V [s][d] used as col-major k x n)
#pragma unroll
        for (int ks = 0; ks < 8; ks++) {
            uint32_t a0 = Pt[(m0 + g) * FPAD + ks * 8 + tg];
            uint32_t a1 = Pt[(m0 + g + 8) * FPAD + ks * 8 + tg];
            uint32_t a2 = Pt[(m0 + g) * FPAD + ks * 8 + tg + 4];
            uint32_t a3 = Pt[(m0 + g + 8) * FPAD + ks * 8 + tg + 4];
#pragma unroll
            for (int nf = 0; nf < 8; nf++) {
                uint32_t b0 = Vs[(ks * 8 + tg) * FPAD + nf * 8 + g];
                uint32_t b1 = Vs[(ks * 8 + tg + 4) * FPAD + nf * 8 + g];
                MMA_TF32(acc_o[nf], a0, a1, a2, a3, b0, b1);
            }
        }
    }

    // normalize and write merged [T*B, E]
    float invA = 1.0f / lA, invB = 1.0f / lB;
#pragma unroll
    for (int nf = 0; nf < 8; nf++) {
        int t = t0 + m0 + g;
        int d = col + nf * 8 + 2 * tg;
        float2 v0 = { acc_o[nf][0] * invA, acc_o[nf][1] * invA };
        *(float2*)(Out + (size_t)(t * BATCH + b) * EMB + d) = v0;
        float2 v1 = { acc_o[nf][2] * invB, acc_o[nf][3] * invB };
        *(float2*)(Out + (size_t)((t + 8) * BATCH + b) * EMB + d) = v1;
    }
}

// ---------------- launch ---------------------------------------------------
extern "C" void kernel_launch(void* const* d_in, const int* in_sizes, int n_in,
                              void* d_out, int out_size)
{
    (void)in_sizes; (void)n_in; (void)out_size;
    const float* g       = (const float*)d_in[0];
    const float* h       = (const float*)d_in[1];
    const float* g_in_w  = (const float*)d_in[2];
    const float* g_in_b  = (const float*)d_in[3];
    const float* h_in_w  = (const float*)d_in[4];
    const float* h_in_b  = (const float*)d_in[5];
    const float* g_out_w = (const float*)d_in[6];
    const float* g_out_b = (const float*)d_in[7];
    const float* h_out_w = (const float*)d_in[8];
    const float* h_out_b = (const float*)d_in[9];
    float* out = (float*)d_out;

    float *qkv, *kvh, *ag, *ah;
    cudaGetSymbolAddress((void**)&qkv, sc_qkv);
    cudaGetSymbolAddress((void**)&kvh, sc_kvh);
    cudaGetSymbolAddress((void**)&ag,  sc_ag);
    cudaGetSymbolAddress((void**)&ah,  sc_ah);

    cudaFuncSetAttribute(flash_mma_dual, cudaFuncAttributeMaxDynamicSharedMemorySize,
                         FLASH_SMEM_BYTES);

    dim3 blk(256);
    // 1) both input projections in one launch (g: N=3072 q-scaled; h: N=2048)
    tf32_gemm_dual<<<dim3(24 + 16, MROWS / 128), blk>>>(
        g, g_in_w, g_in_b, qkv, 3072, 1024, 24,
        h, h_in_w, h_in_b, kvh, 2048, 0);
    // 2) both attention streams in one launch (x-interleaved: even=g, odd=h)
    flash_mma_dual<<<dim3(2 * T_LEN / 128, BH), blk, FLASH_SMEM_BYTES>>>();
    // 3) both output projections in one launch, straight into d_out
    tf32_gemm_dual<<<dim3(8 + 8, MROWS / 128), blk>>>(
        ag, g_out_w, g_out_b, out,               1024, 0, 8,
        ah, h_out_w, h_out_b, out + MROWS * EMB, 1024, 0);
}

// round 16
// speedup vs baseline: 2.9018x; 1.0827x over previous
#include <cuda_runtime.h>
#include <cstdint>
#include <math_constants.h>

#define T_LEN 1024
#define BATCH 2
#define EMB 1024
#define HEADS 16
#define HDIM 64
#define MROWS (T_LEN * BATCH)   // 2048
#define BH (BATCH * HEADS)      // 32

// ---------------- scratch (device globals; no allocation) ----------------
__device__ float sc_qkv[MROWS * 3 * EMB];   // g-stream: q | gk | gv (tf32-rounded)
__device__ float sc_kvh[MROWS * 2 * EMB];   // h-stream: hk | hv     (tf32-rounded)
__device__ float sc_ag[MROWS * EMB];        // merged g attn out     (tf32-rounded)
__device__ float sc_ah[MROWS * EMB];        // merged h attn out     (tf32-rounded)
// tf32-rounded copies of primary inputs
__device__ float sc_rg[MROWS * EMB];
__device__ float sc_rh[MROWS * EMB];
__device__ float sc_w_gin[3 * EMB * EMB];
__device__ float sc_w_hin[2 * EMB * EMB];
__device__ float sc_w_gout[EMB * EMB];
__device__ float sc_w_hout[EMB * EMB];

// ---------------- threefry2x32 (JAX, key = (0, 42)) -----------------------
static __device__ __forceinline__ uint2 threefry2x32_both(uint32_t c0, uint32_t c1) {
    const uint32_t ks1 = 42u;
    const uint32_t ks2 = 0x1BD11BF0u;
    uint32_t x0 = c0;
    uint32_t x1 = c1 + ks1;
#define TF_R(r) { x0 += x1; x1 = __funnelshift_l(x1, x1, (r)); x1 ^= x0; }
    TF_R(13) TF_R(15) TF_R(26) TF_R(6)   x0 += ks1; x1 += ks2 + 1u;
    TF_R(17) TF_R(29) TF_R(16) TF_R(24)  x0 += ks2; x1 += 0u  + 2u;
    TF_R(13) TF_R(15) TF_R(26) TF_R(6)   x0 += 0u;  x1 += ks1 + 3u;
    TF_R(17) TF_R(29) TF_R(16) TF_R(24)  x0 += ks1; x1 += ks2 + 4u;
    TF_R(13) TF_R(15) TF_R(26) TF_R(6)   x0 += ks2; x1 += 0u  + 5u;
#undef TF_R
    return make_uint2(x0, x1);
}

// JAX partitionable mode: counts (0, i); output = w0 ^ w1. (VERIFIED R10)
static __device__ __forceinline__ uint32_t jax_bits(uint32_t idx) {
    uint2 w = threefry2x32_both(0u, idx);
    return w.x ^ w.y;
}

// gumbel noise; inner log via MUFU (__logf) — verified R14
static __device__ __forceinline__ float gumbel_noise(uint32_t idx) {
    uint32_t y = jax_bits(idx);
    float u = __uint_as_float((y >> 9) | 0x3f800000u) - 1.0f;
    float inner = -__logf(u + 1e-20f) + 1e-20f;
    return -__logf(inner);
}

// ---------------- tf32 / cp.async helpers ----------------------------------
static __device__ __forceinline__ uint32_t f2tf32(float f) {
    uint32_t r;
    asm("cvt.rna.tf32.f32 %0, %1;" : "=r"(r) : "f"(f));
    return r;
}
static __device__ __forceinline__ float round_tf32(float f) {
    return __uint_as_float(f2tf32(f));
}
static __device__ __forceinline__ uint32_t smem_u32(const void* p) {
    return (uint32_t)__cvta_generic_to_shared(p);
}
static __device__ __forceinline__ void cp16(uint32_t smem_addr, const void* gptr) {
    asm volatile("cp.async.cg.shared.global [%0], [%1], 16;"
                 :: "r"(smem_addr), "l"(gptr));
}
#define CP_COMMIT() asm volatile("cp.async.commit_group;")
#define CP_WAIT(n)  asm volatile("cp.async.wait_group %0;" :: "n"(n))

#define MMA_TF32(acc, a0, a1, a2, a3, b0, b1)                                  \
    asm volatile(                                                              \
        "mma.sync.aligned.m16n8k8.row.col.f32.tf32.tf32.f32 "                  \
        "{%0,%1,%2,%3}, {%4,%5,%6,%7}, {%8,%9}, {%0,%1,%2,%3};"                \
        : "+f"((acc)[0]), "+f"((acc)[1]), "+f"((acc)[2]), "+f"((acc)[3])       \
        : "r"(a0), "r"(a1), "r"(a2), "r"(a3), "r"(b0), "r"(b1))

// ---------------- pre-pass: round 6 arrays to tf32-representable fp32 ------
__global__ void round_tf32_multi(
    const float* __restrict__ s0, float* __restrict__ d0, int n0,
    const float* __restrict__ s1, float* __restrict__ d1, int n1,
    const float* __restrict__ s2, float* __restrict__ d2, int n2,
    const float* __restrict__ s3, float* __restrict__ d3, int n3,
    const float* __restrict__ s4, float* __restrict__ d4, int n4,
    const float* __restrict__ s5, float* __restrict__ d5, int n5)
{
    const float* s; float* d; int n;
    switch (blockIdx.y) {
        case 0: s = s0; d = d0; n = n0; break;
        case 1: s = s1; d = d1; n = n1; break;
        case 2: s = s2; d = d2; n = n2; break;
        case 3: s = s3; d = d3; n = n3; break;
        case 4: s = s4; d = d4; n = n4; break;
        default: s = s5; d = d5; n = n5; break;
    }
    int stride = gridDim.x * blockDim.x * 4;
    for (int i = (blockIdx.x * blockDim.x + threadIdx.x) * 4; i < n; i += stride) {
        float4 v = *(const float4*)(s + i);
        float4 o = { round_tf32(v.x), round_tf32(v.y), round_tf32(v.z), round_tf32(v.w) };
        *(float4*)(d + i) = o;
    }
}

// ---------------- dual tf32 GEMM, cp.async double-buffered -----------------
// Inputs MUST already be tf32-representable (HMMA truncation is then exact).
// round_out=1 rounds C to tf32 at store (intermediates feeding later MMAs).
#define GS 4608                      // 128*36 uint32 per stage per matrix
#define GEMM_SMEM_BYTES (4 * GS * 4) // 2 stages x (A+B)

__global__ __launch_bounds__(256, 2) void tf32_gemm_dual(
    const float* __restrict__ A0, const float* __restrict__ W0,
    const float* __restrict__ b0, float* __restrict__ C0, int N0, int sc0, int split,
    const float* __restrict__ A1, const float* __restrict__ W1,
    const float* __restrict__ b1, float* __restrict__ C1, int N1, int sc1,
    int round_out)
{
    const int K = 1024;
    extern __shared__ uint32_t dsm[];
    uint32_t* As = dsm;            // [2][128*36]
    uint32_t* Bs = dsm + 2 * GS;   // [2][128*36]

    const float* A; const float* W; const float* bias; float* C;
    int N, scale_cols, bnx;
    if (blockIdx.x < (unsigned)split) {
        A = A0; W = W0; bias = b0; C = C0; N = N0; scale_cols = sc0; bnx = blockIdx.x;
    } else {
        A = A1; W = W1; bias = b1; C = C1; N = N1; scale_cols = sc1; bnx = blockIdx.x - split;
    }
    const int bm = blockIdx.y * 128;
    const int bn = bnx * 128;
    const int tid = threadIdx.x;
    const int lane = tid & 31, warp = tid >> 5;
    const int warpM = warp & 1, warpN = warp >> 1;
    const int mbase = warpM * 64, nbase = warpN * 32;
    const int g = lane >> 2, tg = lane & 3;

    const float* Ab = A + (size_t)bm * K;
    const float* Wb = W + (size_t)bn * K;
    const uint32_t asb = smem_u32(As);
    const uint32_t bsb = smem_u32(Bs);
    // this thread's 4 copy slots: row = idx>>3, col4 = (idx&7)*4
    const int r0 = tid >> 3, c4 = (tid & 7) << 2;   // +32 rows per i

    float acc[4][4][4];
#pragma unroll
    for (int mt = 0; mt < 4; mt++)
#pragma unroll
        for (int nt = 0; nt < 4; nt++)
#pragma unroll
            for (int c = 0; c < 4; c++) acc[mt][nt][c] = 0.f;

    // prologue: stage 0
#pragma unroll
    for (int i = 0; i < 4; i++) {
        int row = r0 + i * 32;
        uint32_t so = (uint32_t)(row * 36 + c4) * 4u;
        cp16(asb + so, Ab + (size_t)row * K + c4);
        cp16(bsb + so, Wb + (size_t)row * K + c4);
    }
    CP_COMMIT();

    const int nk = K / 32;   // 32
    for (int kt = 0; kt < nk; kt++) {
        if (kt + 1 < nk) {
            int st = (kt + 1) & 1;
            int k0 = (kt + 1) * 32;
#pragma unroll
            for (int i = 0; i < 4; i++) {
                int row = r0 + i * 32;
                uint32_t so = (uint32_t)(st * GS + row * 36 + c4) * 4u;
                cp16(asb + so, Ab + (size_t)row * K + k0 + c4);
                cp16(bsb + so, Wb + (size_t)row * K + k0 + c4);
            }
            CP_COMMIT();
            CP_WAIT(1);
        } else {
            CP_WAIT(0);
        }
        __syncthreads();

        const uint32_t* Ast = As + (kt & 1) * GS;
        const uint32_t* Bst = Bs + (kt & 1) * GS;
#pragma unroll
        for (int ks = 0; ks < 32; ks += 8) {
            uint32_t af[4][4], bf[4][2];
#pragma unroll
            for (int mt = 0; mt < 4; mt++) {
                int ro = (mbase + mt * 16 + g) * 36 + ks + tg;
                af[mt][0] = Ast[ro];
                af[mt][1] = Ast[ro + 8 * 36];
                af[mt][2] = Ast[ro + 4];
                af[mt][3] = Ast[ro + 8 * 36 + 4];
            }
#pragma unroll
            for (int nt = 0; nt < 4; nt++) {
                int ro = (nbase + nt * 8 + g) * 36 + ks + tg;
                bf[nt][0] = Bst[ro];
                bf[nt][1] = Bst[ro + 4];
            }
#pragma unroll
            for (int mt = 0; mt < 4; mt++)
#pragma unroll
                for (int nt = 0; nt < 4; nt++)
                    MMA_TF32(acc[mt][nt], af[mt][0], af[mt][1], af[mt][2], af[mt][3],
                             bf[nt][0], bf[nt][1]);
        }
        __syncthreads();
    }

#pragma unroll
    for (int mt = 0; mt < 4; mt++) {
        int row = bm + mbase + mt * 16 + g;
#pragma unroll
        for (int nt = 0; nt < 4; nt++) {
            int c0 = bn + nbase + nt * 8 + 2 * tg;
            float bx = bias[c0], by = bias[c0 + 1];
            float2 v0 = { acc[mt][nt][0] + bx, acc[mt][nt][1] + by };
            float2 v1 = { acc[mt][nt][2] + bx, acc[mt][nt][3] + by };
            if (c0 < scale_cols) {
                v0.x *= 0.125f; v0.y *= 0.125f; v1.x *= 0.125f; v1.y *= 0.125f;
            }
            if (round_out) {
                v0.x = round_tf32(v0.x); v0.y = round_tf32(v0.y);
                v1.x = round_tf32(v1.x); v1.y = round_tf32(v1.y);
            }
            *(float2*)(C + (size_t)row * N + c0) = v0;
            *(float2*)(C + (size_t)(row + 8) * N + c0) = v1;
        }
    }
}

// ---------------- dual tensor-core fused flash attention -------------------
// blockIdx.x & 1 selects stream (0 = g plain, 1 = h gumbel), interleaved for
// per-SM pipe mixing. All inputs tf32-representable -> raw cp.async loads.
// K/V cp.async issued BEFORE the RNG block so threefry hides load latency.
#define FPAD 68
#define SM_Q  0                       // [128][68]
#define SM_K  (128 * FPAD)            // [64][68]
#define SM_V  (128 * FPAD + 64 * FPAD)
#define SM_P  (128 * FPAD + 2 * 64 * FPAD)
#define FLASH_SMEM_BYTES ((2 * 128 * FPAD + 2 * 64 * FPAD) * 4)

__global__ __launch_bounds__(256, 2) void flash_mma_dual()
{
    extern __shared__ uint32_t sm[];
    uint32_t* Qs = sm + SM_Q;
    uint32_t* Ks = sm + SM_K;
    uint32_t* Vs = sm + SM_V;
    uint32_t* Pt = sm + SM_P;
    const uint32_t qsb = smem_u32(Qs);
    const uint32_t ksb = smem_u32(Ks);
    const uint32_t vsb = smem_u32(Vs);

    const int stream = blockIdx.x & 1;          // 0 = g, 1 = h
    const int t0 = (blockIdx.x >> 1) * 128;
    const int bh = blockIdx.y;
    const int b = bh >> 4, hh = bh & 15;
    const int col = hh * HDIM;
    const int tid = threadIdx.x;
    const int lane = tid & 31, warp = tid >> 5;
    const int g = lane >> 2, tg = lane & 3;
    const int m0 = warp * 16;

    const float* KVsrc = stream ? sc_kvh : sc_qkv;
    const int ldkv = stream ? 2048 : 3072;
    const int koff = stream ? 0 : 1024;
    const int voff = stream ? 1024 : 2048;
    float* Out = stream ? sc_ah : sc_ag;
    const bool do_gumbel = (stream == 1);

    // Q tile [128 t][64 j] via cp.async (qkv pre-rounded)
#pragma unroll
    for (int r = 0; r < 8; r++) {
        int fi = r * 256 + tid;
        int row = fi >> 4, jq = (fi & 15) << 2;
        cp16(qsb + (uint32_t)(row * FPAD + jq) * 4u,
             sc_qkv + (size_t)((t0 + row) * BATCH + b) * 3072 + col + jq);
    }
    CP_COMMIT();

    float acc_o[8][4];
#pragma unroll
    for (int nf = 0; nf < 8; nf++)
#pragma unroll
        for (int c = 0; c < 4; c++) acc_o[nf][c] = 0.f;
    float mA = -CUDART_INF_F, mB = -CUDART_INF_F, lA = 0.f, lB = 0.f;

    for (int sk = 0; sk < T_LEN; sk += 64) {
        __syncthreads();   // previous-iter readers of Ks/Vs/Pt done
        // issue K/V tile copies (raw; pre-rounded), then overlap RNG
#pragma unroll
        for (int r = 0; r < 4; r++) {
            int fi = r * 256 + tid;
            int row = fi >> 4, jq = (fi & 15) << 2;
            const float* src = KVsrc + (size_t)((sk + row) * BATCH + b) * ldkv;
            uint32_t so = (uint32_t)(row * FPAD + jq) * 4u;
            cp16(ksb + so, src + koff + col + jq);
            cp16(vsb + so, src + voff + col + jq);
        }
        CP_COMMIT();

        if (do_gumbel) {
            // phase-isolated RNG: 8192 noise values -> Pt[t][s]; 32 per thread
            int r = tid >> 1;
            int cb = (tid & 1) * 32;
            uint32_t ibase = ((uint32_t)bh << 20) + ((uint32_t)(t0 + r) << 10)
                           + (uint32_t)(sk + cb);
            uint32_t* dst = &Pt[r * FPAD + cb];
#pragma unroll
            for (int c = 0; c < 32; c += 8) {
                float n[8];
#pragma unroll
                for (int j = 0; j < 8; j++) n[j] = gumbel_noise(ibase + c + j);
#pragma unroll
                for (int j = 0; j < 8; j++) dst[c + j] = __float_as_uint(n[j]);
            }
        }
        CP_WAIT(0);
        __syncthreads();

        // S = Q @ K^T : warp rows [m0, m0+16), all 64 cols
        float acc_s[8][4];
#pragma unroll
        for (int nf = 0; nf < 8; nf++)
#pragma unroll
            for (int c = 0; c < 4; c++) acc_s[nf][c] = 0.f;
#pragma unroll
        for (int ks = 0; ks < 8; ks++) {
            uint32_t a0 = Qs[(m0 + g) * FPAD + ks * 8 + tg];
            uint32_t a1 = Qs[(m0 + g + 8) * FPAD + ks * 8 + tg];
            uint32_t a2 = Qs[(m0 + g) * FPAD + ks * 8 + tg + 4];
            uint32_t a3 = Qs[(m0 + g + 8) * FPAD + ks * 8 + tg + 4];
#pragma unroll
            for (int nf = 0; nf < 8; nf++) {
                uint32_t b0 = Ks[(nf * 8 + g) * FPAD + ks * 8 + tg];
                uint32_t b1 = Ks[(nf * 8 + g) * FPAD + ks * 8 + tg + 4];
                MMA_TF32(acc_s[nf], a0, a1, a2, a3, b0, b1);
            }
        }

        if (do_gumbel) {
            // add noise from Pt; slot (t,s) owner == this thread (also P writer)
#pragma unroll
            for (int nf = 0; nf < 8; nf++) {
                int iA = (m0 + g) * FPAD + nf * 8 + 2 * tg;
                acc_s[nf][0] += __uint_as_float(Pt[iA]);
                acc_s[nf][1] += __uint_as_float(Pt[iA + 1]);
                int iB = (m0 + g + 8) * FPAD + nf * 8 + 2 * tg;
                acc_s[nf][2] += __uint_as_float(Pt[iB]);
                acc_s[nf][3] += __uint_as_float(Pt[iB + 1]);
            }
        }

        // online softmax: rows (m0+g) [c0,c1] and (m0+g+8) [c2,c3];
        // full row lives in the 4-lane tg quad -> 2 shfls.
        float mxA = -CUDART_INF_F, mxB = -CUDART_INF_F;
#pragma unroll
        for (int nf = 0; nf < 8; nf++) {
            mxA = fmaxf(mxA, fmaxf(acc_s[nf][0], acc_s[nf][1]));
            mxB = fmaxf(mxB, fmaxf(acc_s[nf][2], acc_s[nf][3]));
        }
        mxA = fmaxf(mxA, __shfl_xor_sync(0xffffffffu, mxA, 1));
        mxA = fmaxf(mxA, __shfl_xor_sync(0xffffffffu, mxA, 2));
        mxB = fmaxf(mxB, __shfl_xor_sync(0xffffffffu, mxB, 1));
        mxB = fmaxf(mxB, __shfl_xor_sync(0xffffffffu, mxB, 2));
        float mnA = fmaxf(mA, mxA), mnB = fmaxf(mB, mxB);
        float scA = __expf(mA - mnA), scB = __expf(mB - mnB);
        float rsA = 0.f, rsB = 0.f;
#pragma unroll
        for (int nf = 0; nf < 8; nf++) {
            acc_s[nf][0] = __expf(acc_s[nf][0] - mnA);
            acc_s[nf][1] = __expf(acc_s[nf][1] - mnA);
            acc_s[nf][2] = __expf(acc_s[nf][2] - mnB);
            acc_s[nf][3] = __expf(acc_s[nf][3] - mnB);
            rsA += acc_s[nf][0] + acc_s[nf][1];
            rsB += acc_s[nf][2] + acc_s[nf][3];
        }
        rsA += __shfl_xor_sync(0xffffffffu, rsA, 1);
        rsA += __shfl_xor_sync(0xffffffffu, rsA, 2);
        rsB += __shfl_xor_sync(0xffffffffu, rsB, 1);
        rsB += __shfl_xor_sync(0xffffffffu, rsB, 2);
        lA = lA * scA + rsA;
        lB = lB * scB + rsB;
        mA = mnA; mB = mnB;
#pragma unroll
        for (int nf = 0; nf < 8; nf++) {
            acc_o[nf][0] *= scA; acc_o[nf][1] *= scA;
            acc_o[nf][2] *= scB; acc_o[nf][3] *= scB;
        }

        // stage P (tf32) for the PV mma (same slots this thread read noise from)
#pragma unroll
        for (int nf = 0; nf < 8; nf++) {
            int iA = (m0 + g) * FPAD + nf * 8 + 2 * tg;
            Pt[iA]     = f2tf32(acc_s[nf][0]);
            Pt[iA + 1] = f2tf32(acc_s[nf][1]);
            int iB = (m0 + g + 8) * FPAD + nf * 8 + 2 * tg;
            Pt[iB]     = f2tf32(acc_s[nf][2]);
            Pt[iB + 1] = f2tf32(acc_s[nf][3]);
        }
        __syncthreads();

        // O += P @ V  (A = P [t][s], B = V [s][d] used as col-major k x n)
#pragma unroll
        for (int ks = 0; ks < 8; ks++) {
            uint32_t a0 = Pt[(m0 + g) * FPAD + ks * 8 + tg];
            uint32_t a1 = Pt[(m0 + g + 8) * FPAD + ks * 8 + tg];
            uint32_t a2 = Pt[(m0 + g) * FPAD + ks * 8 + tg + 4];
            uint32_t a3 = Pt[(m0 + g + 8) * FPAD + ks * 8 + tg + 4];
#pragma unroll
            for (int nf = 0; nf < 8; nf++) {
                uint32_t b0 = Vs[(ks * 8 + tg) * FPAD + nf * 8 + g];
                uint32_t b1 = Vs[(ks * 8 + tg + 4) * FPAD + nf * 8 + g];
                MMA_TF32(acc_o[nf], a0, a1, a2, a3, b0, b1);
            }
        }
    }

    // normalize, round to tf32 (feeds output GEMM), write merged [T*B, E]
    float invA = 1.0f / lA, invB = 1.0f / lB;
#pragma unroll
    for (int nf = 0; nf < 8; nf++) {
        int t = t0 + m0 + g;
        int d = col + nf * 8 + 2 * tg;
        float2 v0 = { round_tf32(acc_o[nf][0] * invA), round_tf32(acc_o[nf][1] * invA) };
        *(float2*)(Out + (size_t)(t * BATCH + b) * EMB + d) = v0;
        float2 v1 = { round_tf32(acc_o[nf][2] * invB), round_tf32(acc_o[nf][3] * invB) };
        *(float2*)(Out + (size_t)((t + 8) * BATCH + b) * EMB + d) = v1;
    }
}

// ---------------- launch ---------------------------------------------------
extern "C" void kernel_launch(void* const* d_in, const int* in_sizes, int n_in,
                              void* d_out, int out_size)
{
    (void)in_sizes; (void)n_in; (void)out_size;
    const float* g       = (const float*)d_in[0];
    const float* h       = (const float*)d_in[1];
    const float* g_in_w  = (const float*)d_in[2];
    const float* g_in_b  = (const float*)d_in[3];
    const float* h_in_w  = (const float*)d_in[4];
    const float* h_in_b  = (const float*)d_in[5];
    const float* g_out_w = (const float*)d_in[6];
    const float* g_out_b = (const float*)d_in[7];
    const float* h_out_w = (const float*)d_in[8];
    const float* h_out_b = (const float*)d_in[9];
    float* out = (float*)d_out;

    float *qkv, *kvh, *ag, *ah, *rg, *rh, *wgi, *whi, *wgo, *who;
    cudaGetSymbolAddress((void**)&qkv, sc_qkv);
    cudaGetSymbolAddress((void**)&kvh, sc_kvh);
    cudaGetSymbolAddress((void**)&ag,  sc_ag);
    cudaGetSymbolAddress((void**)&ah,  sc_ah);
    cudaGetSymbolAddress((void**)&rg,  sc_rg);
    cudaGetSymbolAddress((void**)&rh,  sc_rh);
    cudaGetSymbolAddress((void**)&wgi, sc_w_gin);
    cudaGetSymbolAddress((void**)&whi, sc_w_hin);
    cudaGetSymbolAddress((void**)&wgo, sc_w_gout);
    cudaGetSymbolAddress((void**)&who, sc_w_hout);

    cudaFuncSetAttribute(flash_mma_dual, cudaFuncAttributeMaxDynamicSharedMemorySize,
                         FLASH_SMEM_BYTES);
    cudaFuncSetAttribute(tf32_gemm_dual, cudaFuncAttributeMaxDynamicSharedMemorySize,
                         GEMM_SMEM_BYTES);

    dim3 blk(256);
    // 0) round primary inputs to tf32-representable fp32 (~15 us)
    round_tf32_multi<<<dim3(128, 6), blk>>>(
        g, rg, MROWS * EMB,
        h, rh, MROWS * EMB,
        g_in_w, wgi, 3 * EMB * EMB,
        h_in_w, whi, 2 * EMB * EMB,
        g_out_w, wgo, EMB * EMB,
        h_out_w, who, EMB * EMB);
    // 1) both input projections (g: N=3072 q-scaled; h: N=2048), rounded out
    tf32_gemm_dual<<<dim3(24 + 16, MROWS / 128), blk, GEMM_SMEM_BYTES>>>(
        rg, wgi, g_in_b, qkv, 3072, 1024, 24,
        rh, whi, h_in_b, kvh, 2048, 0, 1);
    // 2) both attention streams in one launch (x-interleaved: even=g, odd=h)
    flash_mma_dual<<<dim3(2 * T_LEN / 128, BH), blk, FLASH_SMEM_BYTES>>>();
    // 3) both output projections into d_out (final: no rounding)
    tf32_gemm_dual<<<dim3(8 + 8, MROWS / 128), blk, GEMM_SMEM_BYTES>>>(
        ag, wgo, g_out_b, out,               1024, 0, 8,
        ah, who, h_out_b, out + MROWS * EMB, 1024, 0, 0);
}